// round 1
// baseline (speedup 1.0000x reference)
#include <cuda_runtime.h>
#include <math.h>

#define Bb 4
#define Ss 4096
#define Dd 1024
#define Hh 8
#define DI 2048
#define HD 256
#define Mm (Bb * Ss)   // 16384 tokens

// ---------------- scratch (no allocations allowed) ----------------
__device__ float g_xn[(size_t)Mm * Dd];          //  64 MB
__device__ float g_xz[(size_t)Mm * 2 * DI];      // 256 MB
__device__ float g_act[(size_t)Mm * DI];         // 128 MB

// ---------------- LayerNorm: one block per token ----------------
__global__ void __launch_bounds__(256) ln_kernel(const float* __restrict__ x,
                                                 const float* __restrict__ w,
                                                 const float* __restrict__ bia) {
    int m = blockIdx.x;
    int t = threadIdx.x;
    const float4* xr = (const float4*)(x + (size_t)m * Dd);
    float4 xv = xr[t];                       // 256 threads * 4 = 1024
    float s  = xv.x + xv.y + xv.z + xv.w;
    float s2 = xv.x * xv.x + xv.y * xv.y + xv.z * xv.z + xv.w * xv.w;
    #pragma unroll
    for (int o = 16; o; o >>= 1) {
        s  += __shfl_xor_sync(0xffffffffu, s, o);
        s2 += __shfl_xor_sync(0xffffffffu, s2, o);
    }
    __shared__ float shs[8], shs2[8];
    int wid = t >> 5, lane = t & 31;
    if (lane == 0) { shs[wid] = s; shs2[wid] = s2; }
    __syncthreads();
    s = 0.f; s2 = 0.f;
    #pragma unroll
    for (int i = 0; i < 8; i++) { s += shs[i]; s2 += shs2[i]; }
    float mu  = s * (1.0f / Dd);
    float var = s2 * (1.0f / Dd) - mu * mu;
    float rstd = rsqrtf(var + 1e-5f);
    float4 wv = ((const float4*)w)[t];
    float4 bv = ((const float4*)bia)[t];
    float4 o;
    o.x = (xv.x - mu) * rstd * wv.x + bv.x;
    o.y = (xv.y - mu) * rstd * wv.y + bv.y;
    o.z = (xv.z - mu) * rstd * wv.z + bv.z;
    o.w = (xv.w - mu) * rstd * wv.w + bv.w;
    ((float4*)(g_xn + (size_t)m * Dd))[t] = o;
}

// ---------------- classic 128x128x8 SGEMM, C[m,n] = sum_k A[m,k]*B[n,k] ----------------
// A: MxK row-major, B: NxK row-major (weights). Optional residual add.
template <int N, int K, bool RES>
__device__ __forceinline__ void gemm_body(const float* __restrict__ A,
                                          const float* __restrict__ Bw,
                                          const float* __restrict__ res,
                                          float* __restrict__ C) {
    __shared__ float As[8][132];
    __shared__ float Bs[8][132];
    int tid = threadIdx.x;
    int tx = tid & 15, ty = tid >> 4;
    int bm = blockIdx.y * 128, bn = blockIdx.x * 128;

    int lrow = tid >> 1;            // 0..127
    int lcol = (tid & 1) * 4;       // 0 or 4
    const float* Ap = A  + (size_t)(bm + lrow) * K + lcol;
    const float* Bp = Bw + (size_t)(bn + lrow) * K + lcol;

    float acc[8][8];
    #pragma unroll
    for (int i = 0; i < 8; i++)
        #pragma unroll
        for (int j = 0; j < 8; j++) acc[i][j] = 0.f;

    for (int k0 = 0; k0 < K; k0 += 8) {
        float4 av = *(const float4*)(Ap + k0);
        float4 bv = *(const float4*)(Bp + k0);
        As[lcol + 0][lrow] = av.x; As[lcol + 1][lrow] = av.y;
        As[lcol + 2][lrow] = av.z; As[lcol + 3][lrow] = av.w;
        Bs[lcol + 0][lrow] = bv.x; Bs[lcol + 1][lrow] = bv.y;
        Bs[lcol + 2][lrow] = bv.z; Bs[lcol + 3][lrow] = bv.w;
        __syncthreads();
        #pragma unroll
        for (int k = 0; k < 8; k++) {
            float4 a0 = *(const float4*)&As[k][ty * 4];
            float4 a1 = *(const float4*)&As[k][64 + ty * 4];
            float4 b0 = *(const float4*)&Bs[k][tx * 4];
            float4 b1 = *(const float4*)&Bs[k][64 + tx * 4];
            float af[8] = {a0.x, a0.y, a0.z, a0.w, a1.x, a1.y, a1.z, a1.w};
            float bf[8] = {b0.x, b0.y, b0.z, b0.w, b1.x, b1.y, b1.z, b1.w};
            #pragma unroll
            for (int i = 0; i < 8; i++)
                #pragma unroll
                for (int j = 0; j < 8; j++)
                    acc[i][j] = fmaf(af[i], bf[j], acc[i][j]);
        }
        __syncthreads();
    }

    #pragma unroll
    for (int i = 0; i < 8; i++) {
        int m = bm + ((i < 4) ? (ty * 4 + i) : (64 + ty * 4 + (i - 4)));
        float* Cr = C + (size_t)m * N;
        int n0 = bn + tx * 4;
        int n1 = bn + 64 + tx * 4;
        float4 v0 = make_float4(acc[i][0], acc[i][1], acc[i][2], acc[i][3]);
        float4 v1 = make_float4(acc[i][4], acc[i][5], acc[i][6], acc[i][7]);
        if (RES) {
            const float* Rr = res + (size_t)m * N;
            float4 r0 = *(const float4*)(Rr + n0);
            float4 r1 = *(const float4*)(Rr + n1);
            v0.x += r0.x; v0.y += r0.y; v0.z += r0.z; v0.w += r0.w;
            v1.x += r1.x; v1.y += r1.y; v1.z += r1.z; v1.w += r1.w;
        }
        *(float4*)(Cr + n0) = v0;
        *(float4*)(Cr + n1) = v1;
    }
}

__global__ void __launch_bounds__(256) gemm1_kernel(const float* __restrict__ W) {
    gemm_body<2 * DI, Dd, false>(g_xn, W, nullptr, g_xz);
}

__global__ void __launch_bounds__(256) gemm2_kernel(const float* __restrict__ W,
                                                    const float* __restrict__ res,
                                                    float* __restrict__ out) {
    gemm_body<Dd, DI, true>(g_act, W, res, out);
}

// ---------------- fused causal conv(4) + linear recurrence + SiLU*gate ----------------
// one thread per (batch, channel): 4*2048 = 8192 sequences of length 4096
__global__ void __launch_bounds__(64) scan_kernel(const float* __restrict__ conv_w,
                                                  const float* __restrict__ conv_b,
                                                  const float* __restrict__ log_alpha) {
    int idx = blockIdx.x * 64 + threadIdx.x;   // 0..8191
    int c = idx & (DI - 1);
    int b = idx / DI;
    float w0 = conv_w[c * 4 + 0];
    float w1 = conv_w[c * 4 + 1];
    float w2 = conv_w[c * 4 + 2];
    float w3 = conv_w[c * 4 + 3];
    float bias = conv_b[c];
    float la = log_alpha[c / HD];
    float alpha = 1.f / (1.f + expf(-la));

    const float* xp = g_xz + (size_t)b * Ss * (2 * DI) + c;        // x_path stream
    const float* gp = xp + DI;                                     // gate stream
    float* ap = g_act + (size_t)b * Ss * DI + c;

    float h0 = 0.f, h1 = 0.f, h2 = 0.f, y = 0.f;
    for (int t = 0; t < Ss; t++) {
        float xt = xp[(size_t)t * (2 * DI)];
        float g  = gp[(size_t)t * (2 * DI)];
        float cv = fmaf(w0, h0, fmaf(w1, h1, fmaf(w2, h2, fmaf(w3, xt, bias))));
        h0 = h1; h1 = h2; h2 = xt;
        y = fmaf(alpha, y, cv);
        float sl = y * (1.f / (1.f + __expf(-y)));
        ap[(size_t)t * DI] = sl * g;
    }
}

// ---------------- launch ----------------
extern "C" void kernel_launch(void* const* d_in, const int* in_sizes, int n_in,
                              void* d_out, int out_size) {
    const float* x          = (const float*)d_in[0];
    const float* norm_w     = (const float*)d_in[1];
    const float* norm_b     = (const float*)d_in[2];
    const float* in_proj_w  = (const float*)d_in[3];
    const float* conv_w     = (const float*)d_in[4];
    const float* conv_b     = (const float*)d_in[5];
    const float* out_proj_w = (const float*)d_in[6];
    const float* log_alpha  = (const float*)d_in[7];
    float* out = (float*)d_out;

    ln_kernel<<<Mm, 256>>>(x, norm_w, norm_b);

    dim3 g1((2 * DI) / 128, Mm / 128);           // (32, 128)
    gemm1_kernel<<<g1, 256>>>(in_proj_w);

    scan_kernel<<<(Bb * DI) / 64, 64>>>(conv_w, conv_b, log_alpha);

    dim3 g2(Dd / 128, Mm / 128);                 // (8, 128)
    gemm2_kernel<<<g2, 256>>>(out_proj_w, x, out);
}

// round 6
// speedup vs baseline: 1.6810x; 1.6810x over previous
#include <cuda_runtime.h>
#include <cuda_bf16.h>
#include <math.h>
#include <stdint.h>

#define Bb 4
#define Ss 4096
#define Dd 1024
#define DI 2048
#define HD 256
#define Mm (Bb * Ss)   // 16384 tokens

// ---------------- scratch (device-code references ONLY; never named in host code) ----
__device__ float g_xz[(size_t)Mm * 2 * DI];                 // 256 MB (gemm1 out, fp32)
__device__ __nv_bfloat16 g_xn_hi[(size_t)Mm * Dd];          // 32 MB
__device__ __nv_bfloat16 g_xn_lo[(size_t)Mm * Dd];          // 32 MB
__device__ __nv_bfloat16 g_act_hi[(size_t)Mm * DI];         // 64 MB
__device__ __nv_bfloat16 g_act_lo[(size_t)Mm * DI];         // 64 MB
__device__ __nv_bfloat16 g_w1_hi[(size_t)2 * DI * Dd];      //  8 MB
__device__ __nv_bfloat16 g_w1_lo[(size_t)2 * DI * Dd];      //  8 MB
__device__ __nv_bfloat16 g_w2_hi[(size_t)Dd * DI];          //  4 MB
__device__ __nv_bfloat16 g_w2_lo[(size_t)Dd * DI];          //  4 MB

// ================= helpers =================
__device__ __forceinline__ uint32_t smem_u32(const void* p) {
    uint32_t a;
    asm("{ .reg .u64 t; cvta.to.shared.u64 t, %1; cvt.u32.u64 %0, t; }" : "=r"(a) : "l"(p));
    return a;
}
__device__ __forceinline__ void bsplit(float x, __nv_bfloat16& h, __nv_bfloat16& l) {
    h = __float2bfloat16(x);
    l = __float2bfloat16(x - __bfloat162float(h));
}
__device__ __forceinline__ void cp16(uint32_t dst, const void* src) {
    asm volatile("cp.async.cg.shared.global [%0], [%1], 16;" :: "r"(dst), "l"(src));
}
__device__ __forceinline__ void cp_commit() { asm volatile("cp.async.commit_group;" ::: "memory"); }
template <int N> __device__ __forceinline__ void cp_wait() {
    asm volatile("cp.async.wait_group %0;" :: "n"(N) : "memory");
}
// bf16 m16n8k16: d(f32) += a(bf16x2 x4) * b(bf16x2 x2)
__device__ __forceinline__ void mma_bf16(float* d, const uint32_t* a, const uint32_t* b) {
    asm volatile(
        "mma.sync.aligned.m16n8k16.row.col.f32.bf16.bf16.f32 "
        "{%0,%1,%2,%3}, {%4,%5,%6,%7}, {%8,%9}, {%0,%1,%2,%3};"
        : "+f"(d[0]), "+f"(d[1]), "+f"(d[2]), "+f"(d[3])
        : "r"(a[0]), "r"(a[1]), "r"(a[2]), "r"(a[3]), "r"(b[0]), "r"(b[1]));
}

// ---------------- weight split to bf16 hi/lo (globals chosen in DEVICE code) --------
template <int WHICH>
__global__ void __launch_bounds__(256) wprep(const float* __restrict__ s) {
    __nv_bfloat16* dh = (WHICH == 1) ? g_w1_hi : g_w2_hi;
    __nv_bfloat16* dl = (WHICH == 1) ? g_w1_lo : g_w2_lo;
    const int n4 = (WHICH == 1) ? (2 * DI * Dd / 4) : (Dd * DI / 4);
    int i = blockIdx.x * 256 + threadIdx.x;
    if (i < n4) {
        float4 v = ((const float4*)s)[i];
        __nv_bfloat16 h[4], l[4];
        bsplit(v.x, h[0], l[0]); bsplit(v.y, h[1], l[1]);
        bsplit(v.z, h[2], l[2]); bsplit(v.w, h[3], l[3]);
        *(__nv_bfloat162*)(dh + (size_t)i * 4)     = __nv_bfloat162(h[0], h[1]);
        *(__nv_bfloat162*)(dh + (size_t)i * 4 + 2) = __nv_bfloat162(h[2], h[3]);
        *(__nv_bfloat162*)(dl + (size_t)i * 4)     = __nv_bfloat162(l[0], l[1]);
        *(__nv_bfloat162*)(dl + (size_t)i * 4 + 2) = __nv_bfloat162(l[2], l[3]);
    }
}

// ---------------- LayerNorm (writes bf16 hi/lo planes) ----------------
__global__ void __launch_bounds__(256) ln_kernel(const float* __restrict__ x,
                                                 const float* __restrict__ w,
                                                 const float* __restrict__ bia) {
    int m = blockIdx.x;
    int t = threadIdx.x;
    const float4* xr = (const float4*)(x + (size_t)m * Dd);
    float4 xv = xr[t];
    float s  = xv.x + xv.y + xv.z + xv.w;
    float s2 = xv.x * xv.x + xv.y * xv.y + xv.z * xv.z + xv.w * xv.w;
    #pragma unroll
    for (int o = 16; o; o >>= 1) {
        s  += __shfl_xor_sync(0xffffffffu, s, o);
        s2 += __shfl_xor_sync(0xffffffffu, s2, o);
    }
    __shared__ float shs[8], shs2[8];
    int wid = t >> 5, lane = t & 31;
    if (lane == 0) { shs[wid] = s; shs2[wid] = s2; }
    __syncthreads();
    s = 0.f; s2 = 0.f;
    #pragma unroll
    for (int i = 0; i < 8; i++) { s += shs[i]; s2 += shs2[i]; }
    float mu  = s * (1.0f / Dd);
    float var = s2 * (1.0f / Dd) - mu * mu;
    float rstd = rsqrtf(var + 1e-5f);
    float4 wv = ((const float4*)w)[t];
    float4 bv = ((const float4*)bia)[t];
    float o0 = (xv.x - mu) * rstd * wv.x + bv.x;
    float o1 = (xv.y - mu) * rstd * wv.y + bv.y;
    float o2 = (xv.z - mu) * rstd * wv.z + bv.z;
    float o3 = (xv.w - mu) * rstd * wv.w + bv.w;
    __nv_bfloat16 h[4], l[4];
    bsplit(o0, h[0], l[0]); bsplit(o1, h[1], l[1]);
    bsplit(o2, h[2], l[2]); bsplit(o3, h[3], l[3]);
    size_t base = (size_t)m * Dd + 4 * t;
    *(__nv_bfloat162*)(g_xn_hi + base)     = __nv_bfloat162(h[0], h[1]);
    *(__nv_bfloat162*)(g_xn_hi + base + 2) = __nv_bfloat162(h[2], h[3]);
    *(__nv_bfloat162*)(g_xn_lo + base)     = __nv_bfloat162(l[0], l[1]);
    *(__nv_bfloat162*)(g_xn_lo + base + 2) = __nv_bfloat162(l[2], l[3]);
}

// ============ bf16 split-GEMM: C[m,n] = sum_k A[m,k]*W[n,k] (+res) ============
// Block 128x128, BK=16, 3-stage cp.async pipeline, 8 warps (4m x 2n), warp 32x64.
// smem per stage: 4 planes (A_hi, A_lo, B_hi, B_lo), 128 rows x 8 u32 (bf16x2) each.
// word swizzle: phys_w = w ^ (row & 4) -> conflict-free fragment LDS.
#define PLANE_U32 (128 * 8)                 // 1024 u32 = 4096 B
#define STAGE_U32 (4 * PLANE_U32)           // 4096 u32 = 16384 B
#define GEMM_SMEM (3 * STAGE_U32 * 4)       // 49152 B

template <int WHICH>                         // 1: xn @ w1 -> g_xz ; 2: act @ w2 + R -> C
__global__ void __launch_bounds__(256, 2) gemm_bf(const float* __restrict__ R,
                                                  float* __restrict__ Cout) {
    constexpr int NTOT = (WHICH == 1) ? 2 * DI : Dd;
    constexpr int KK   = (WHICH == 1) ? Dd : DI;
    constexpr bool RESADD = (WHICH == 2);
    const __nv_bfloat16* Ah = (WHICH == 1) ? g_xn_hi : g_act_hi;
    const __nv_bfloat16* Al = (WHICH == 1) ? g_xn_lo : g_act_lo;
    const __nv_bfloat16* Wh = (WHICH == 1) ? g_w1_hi : g_w2_hi;
    const __nv_bfloat16* Wl = (WHICH == 1) ? g_w1_lo : g_w2_lo;
    float* C = (WHICH == 1) ? g_xz : Cout;

    extern __shared__ uint32_t sm[];
    uint32_t sb = smem_u32(sm);
    int tid = threadIdx.x, lane = tid & 31, wid = tid >> 5;
    int wm = wid & 3, wn = wid >> 2;
    int bm = blockIdx.y * 128, bn = blockIdx.x * 128;
    int lr = lane >> 2, lc = lane & 3;

    // producer coords: row r (0..127), 16B half (8 bf16)
    int r = tid >> 1, half = tid & 1;
    const __nv_bfloat16* pAh = Ah + (size_t)(bm + r) * KK + half * 8;
    const __nv_bfloat16* pAl = Al + (size_t)(bm + r) * KK + half * 8;
    const __nv_bfloat16* pBh = Wh + (size_t)(bn + r) * KK + half * 8;
    const __nv_bfloat16* pBl = Wl + (size_t)(bn + r) * KK + half * 8;
    uint32_t dword = (uint32_t)(r * 8 + (((half << 2) ^ (r & 4)) & 7));
    uint32_t dAh = sb + dword * 4;
    uint32_t dAl = dAh + PLANE_U32 * 4;
    uint32_t dBh = dAh + 2 * PLANE_U32 * 4;
    uint32_t dBl = dAh + 3 * PLANE_U32 * 4;

    const int NIT = KK / 16;
    #define ISSUE(s, k0) do {                          \
        cp16(dAh + (s) * STAGE_U32 * 4, pAh + (k0));   \
        cp16(dAl + (s) * STAGE_U32 * 4, pAl + (k0));   \
        cp16(dBh + (s) * STAGE_U32 * 4, pBh + (k0));   \
        cp16(dBl + (s) * STAGE_U32 * 4, pBl + (k0));   \
        cp_commit();                                   \
    } while (0)

    ISSUE(0, 0);
    ISSUE(1, 16);

    float acc[2][8][4];
    #pragma unroll
    for (int mt = 0; mt < 2; mt++)
        #pragma unroll
        for (int nt = 0; nt < 8; nt++)
            #pragma unroll
            for (int q = 0; q < 4; q++) acc[mt][nt][q] = 0.f;

    for (int i = 0; i < NIT; i++) {
        int s = i % 3;
        if (i + 1 < NIT) cp_wait<1>(); else cp_wait<0>();
        __syncthreads();
        if (i + 2 < NIT) ISSUE((i + 2) % 3, (i + 2) * 16);

        const uint32_t* Sh = sm + s * STAGE_U32;        // A hi
        const uint32_t* Sl = Sh + PLANE_U32;            // A lo
        const uint32_t* Th = Sh + 2 * PLANE_U32;        // B hi
        const uint32_t* Tl = Sh + 3 * PLANE_U32;        // B lo

        uint32_t ah[2][4], al[2][4];
        #pragma unroll
        for (int mt = 0; mt < 2; mt++) {
            int ar0 = wm * 32 + mt * 16 + lr, ar1 = ar0 + 8;
            int w0 = lc ^ (ar0 & 4);
            int w1 = (lc + 4) ^ (ar0 & 4);
            ah[mt][0] = Sh[ar0 * 8 + w0]; ah[mt][1] = Sh[ar1 * 8 + w0];
            ah[mt][2] = Sh[ar0 * 8 + w1]; ah[mt][3] = Sh[ar1 * 8 + w1];
            al[mt][0] = Sl[ar0 * 8 + w0]; al[mt][1] = Sl[ar1 * 8 + w0];
            al[mt][2] = Sl[ar0 * 8 + w1]; al[mt][3] = Sl[ar1 * 8 + w1];
        }
        #pragma unroll
        for (int nt = 0; nt < 8; nt++) {
            int br = wn * 64 + nt * 8 + lr;
            int w0 = lc ^ (br & 4);
            int w1 = (lc + 4) ^ (br & 4);
            uint32_t bh[2] = { Th[br * 8 + w0], Th[br * 8 + w1] };
            uint32_t bl[2] = { Tl[br * 8 + w0], Tl[br * 8 + w1] };
            #pragma unroll
            for (int mt = 0; mt < 2; mt++) {
                mma_bf16(acc[mt][nt], ah[mt], bh);   // hi*hi
                mma_bf16(acc[mt][nt], al[mt], bh);   // lo*hi
                mma_bf16(acc[mt][nt], ah[mt], bl);   // hi*lo
            }
        }
    }
    #undef ISSUE

    // epilogue
    #pragma unroll
    for (int mt = 0; mt < 2; mt++) {
        int m0 = bm + wm * 32 + mt * 16 + lr;
        #pragma unroll
        for (int nt = 0; nt < 8; nt++) {
            int n = bn + wn * 64 + nt * 8 + lc * 2;
            float* C0 = C + (size_t)m0 * NTOT + n;
            float* C1 = C + (size_t)(m0 + 8) * NTOT + n;
            float2 v0 = make_float2(acc[mt][nt][0], acc[mt][nt][1]);
            float2 v1 = make_float2(acc[mt][nt][2], acc[mt][nt][3]);
            if (RESADD) {
                const float2 r0 = *(const float2*)(R + (size_t)m0 * NTOT + n);
                const float2 r1 = *(const float2*)(R + (size_t)(m0 + 8) * NTOT + n);
                v0.x += r0.x; v0.y += r0.y;
                v1.x += r1.x; v1.y += r1.y;
            }
            *(float2*)C0 = v0;
            *(float2*)C1 = v1;
        }
    }
}

// ---------------- fused causal conv(4) + linear recurrence + SiLU*gate ----------------
__global__ void __launch_bounds__(64) scan_kernel(const float* __restrict__ conv_w,
                                                  const float* __restrict__ conv_b,
                                                  const float* __restrict__ log_alpha) {
    int idx = blockIdx.x * 64 + threadIdx.x;   // 0..8191
    int c = idx & (DI - 1);
    int b = idx / DI;
    float w0 = conv_w[c * 4 + 0];
    float w1 = conv_w[c * 4 + 1];
    float w2 = conv_w[c * 4 + 2];
    float w3 = conv_w[c * 4 + 3];
    float bias = conv_b[c];
    float la = log_alpha[c / HD];
    float alpha = 1.f / (1.f + expf(-la));

    const float* xp = g_xz + (size_t)b * Ss * (2 * DI) + c;
    const float* gp = xp + DI;
    size_t ao = (size_t)b * Ss * DI + c;

    float h0 = 0.f, h1 = 0.f, h2 = 0.f, y = 0.f;
    for (int t = 0; t < Ss; t++) {
        float xt = xp[(size_t)t * (2 * DI)];
        float g  = gp[(size_t)t * (2 * DI)];
        float cv = fmaf(w0, h0, fmaf(w1, h1, fmaf(w2, h2, fmaf(w3, xt, bias))));
        h0 = h1; h1 = h2; h2 = xt;
        y = fmaf(alpha, y, cv);
        float sl = y * (1.f / (1.f + __expf(-y)));
        float v = sl * g;
        __nv_bfloat16 hh, ll;
        bsplit(v, hh, ll);
        g_act_hi[ao + (size_t)t * DI] = hh;
        g_act_lo[ao + (size_t)t * DI] = ll;
    }
}

// ---------------- launch (NO device-symbol references in host code) ----------------
extern "C" void kernel_launch(void* const* d_in, const int* in_sizes, int n_in,
                              void* d_out, int out_size) {
    const float* x          = (const float*)d_in[0];
    const float* norm_w     = (const float*)d_in[1];
    const float* norm_b     = (const float*)d_in[2];
    const float* in_proj_w  = (const float*)d_in[3];
    const float* conv_w     = (const float*)d_in[4];
    const float* conv_b     = (const float*)d_in[5];
    const float* out_proj_w = (const float*)d_in[6];
    const float* log_alpha  = (const float*)d_in[7];
    float* out = (float*)d_out;

    cudaFuncSetAttribute(gemm_bf<1>, cudaFuncAttributeMaxDynamicSharedMemorySize, GEMM_SMEM);
    cudaFuncSetAttribute(gemm_bf<2>, cudaFuncAttributeMaxDynamicSharedMemorySize, GEMM_SMEM);

    int n1 = 2 * DI * Dd / 4, n2 = Dd * DI / 4;
    wprep<1><<<(n1 + 255) / 256, 256>>>(in_proj_w);
    wprep<2><<<(n2 + 255) / 256, 256>>>(out_proj_w);

    ln_kernel<<<Mm, 256>>>(x, norm_w, norm_b);

    dim3 g1((2 * DI) / 128, Mm / 128);           // (32, 128)
    gemm_bf<1><<<g1, 256, GEMM_SMEM>>>(nullptr, nullptr);

    scan_kernel<<<(Bb * DI) / 64, 64>>>(conv_w, conv_b, log_alpha);

    dim3 g2(Dd / 128, Mm / 128);                 // (8, 128)
    gemm_bf<2><<<g2, 256, GEMM_SMEM>>>(x, out);
}

// round 7
// speedup vs baseline: 3.6700x; 2.1832x over previous
#include <cuda_runtime.h>
#include <cuda_bf16.h>
#include <math.h>
#include <stdint.h>

#define Bb 4
#define Ss 4096
#define Dd 1024
#define DI 2048
#define HD 256
#define Mm (Bb * Ss)   // 16384 tokens
#define CL 64          // scan chunk length
#define NC (Ss / CL)   // 64 chunks

// ---------------- scratch (device-code references ONLY; never named in host code) ----
__device__ float g_xz[(size_t)Mm * 2 * DI];                 // 256 MB (gemm1 out, fp32)
__device__ __nv_bfloat16 g_xn_hi[(size_t)Mm * Dd];          // 32 MB
__device__ __nv_bfloat16 g_xn_lo[(size_t)Mm * Dd];          // 32 MB
__device__ __nv_bfloat16 g_act_hi[(size_t)Mm * DI];         // 64 MB
__device__ __nv_bfloat16 g_act_lo[(size_t)Mm * DI];         // 64 MB
__device__ __nv_bfloat16 g_w1_hi[(size_t)2 * DI * Dd];      //  8 MB
__device__ __nv_bfloat16 g_w1_lo[(size_t)2 * DI * Dd];      //  8 MB
__device__ __nv_bfloat16 g_w2_hi[(size_t)Dd * DI];          //  4 MB
__device__ __nv_bfloat16 g_w2_lo[(size_t)Dd * DI];          //  4 MB
__device__ float g_e[(size_t)Bb * NC * DI];                 //  2 MB (chunk end values)
__device__ float g_s[(size_t)Bb * NC * DI];                 //  2 MB (chunk init states)

// ================= helpers =================
__device__ __forceinline__ uint32_t smem_u32(const void* p) {
    uint32_t a;
    asm("{ .reg .u64 t; cvta.to.shared.u64 t, %1; cvt.u32.u64 %0, t; }" : "=r"(a) : "l"(p));
    return a;
}
__device__ __forceinline__ void bsplit(float x, __nv_bfloat16& h, __nv_bfloat16& l) {
    h = __float2bfloat16(x);
    l = __float2bfloat16(x - __bfloat162float(h));
}
__device__ __forceinline__ void cp16(uint32_t dst, const void* src) {
    asm volatile("cp.async.cg.shared.global [%0], [%1], 16;" :: "r"(dst), "l"(src));
}
__device__ __forceinline__ void cp_commit() { asm volatile("cp.async.commit_group;" ::: "memory"); }
template <int N> __device__ __forceinline__ void cp_wait() {
    asm volatile("cp.async.wait_group %0;" :: "n"(N) : "memory");
}
__device__ __forceinline__ void mma_bf16(float* d, const uint32_t* a, const uint32_t* b) {
    asm volatile(
        "mma.sync.aligned.m16n8k16.row.col.f32.bf16.bf16.f32 "
        "{%0,%1,%2,%3}, {%4,%5,%6,%7}, {%8,%9}, {%0,%1,%2,%3};"
        : "+f"(d[0]), "+f"(d[1]), "+f"(d[2]), "+f"(d[3])
        : "r"(a[0]), "r"(a[1]), "r"(a[2]), "r"(a[3]), "r"(b[0]), "r"(b[1]));
}

// ---------------- weight split to bf16 hi/lo ----------------
template <int WHICH>
__global__ void __launch_bounds__(256) wprep(const float* __restrict__ s) {
    __nv_bfloat16* dh = (WHICH == 1) ? g_w1_hi : g_w2_hi;
    __nv_bfloat16* dl = (WHICH == 1) ? g_w1_lo : g_w2_lo;
    const int n4 = (WHICH == 1) ? (2 * DI * Dd / 4) : (Dd * DI / 4);
    int i = blockIdx.x * 256 + threadIdx.x;
    if (i < n4) {
        float4 v = ((const float4*)s)[i];
        __nv_bfloat16 h[4], l[4];
        bsplit(v.x, h[0], l[0]); bsplit(v.y, h[1], l[1]);
        bsplit(v.z, h[2], l[2]); bsplit(v.w, h[3], l[3]);
        *(__nv_bfloat162*)(dh + (size_t)i * 4)     = __nv_bfloat162(h[0], h[1]);
        *(__nv_bfloat162*)(dh + (size_t)i * 4 + 2) = __nv_bfloat162(h[2], h[3]);
        *(__nv_bfloat162*)(dl + (size_t)i * 4)     = __nv_bfloat162(l[0], l[1]);
        *(__nv_bfloat162*)(dl + (size_t)i * 4 + 2) = __nv_bfloat162(l[2], l[3]);
    }
}

// ---------------- LayerNorm (writes bf16 hi/lo planes) ----------------
__global__ void __launch_bounds__(256) ln_kernel(const float* __restrict__ x,
                                                 const float* __restrict__ w,
                                                 const float* __restrict__ bia) {
    int m = blockIdx.x;
    int t = threadIdx.x;
    const float4* xr = (const float4*)(x + (size_t)m * Dd);
    float4 xv = xr[t];
    float s  = xv.x + xv.y + xv.z + xv.w;
    float s2 = xv.x * xv.x + xv.y * xv.y + xv.z * xv.z + xv.w * xv.w;
    #pragma unroll
    for (int o = 16; o; o >>= 1) {
        s  += __shfl_xor_sync(0xffffffffu, s, o);
        s2 += __shfl_xor_sync(0xffffffffu, s2, o);
    }
    __shared__ float shs[8], shs2[8];
    int wid = t >> 5, lane = t & 31;
    if (lane == 0) { shs[wid] = s; shs2[wid] = s2; }
    __syncthreads();
    s = 0.f; s2 = 0.f;
    #pragma unroll
    for (int i = 0; i < 8; i++) { s += shs[i]; s2 += shs2[i]; }
    float mu  = s * (1.0f / Dd);
    float var = s2 * (1.0f / Dd) - mu * mu;
    float rstd = rsqrtf(var + 1e-5f);
    float4 wv = ((const float4*)w)[t];
    float4 bv = ((const float4*)bia)[t];
    float o0 = (xv.x - mu) * rstd * wv.x + bv.x;
    float o1 = (xv.y - mu) * rstd * wv.y + bv.y;
    float o2 = (xv.z - mu) * rstd * wv.z + bv.z;
    float o3 = (xv.w - mu) * rstd * wv.w + bv.w;
    __nv_bfloat16 h[4], l[4];
    bsplit(o0, h[0], l[0]); bsplit(o1, h[1], l[1]);
    bsplit(o2, h[2], l[2]); bsplit(o3, h[3], l[3]);
    size_t base = (size_t)m * Dd + 4 * t;
    *(__nv_bfloat162*)(g_xn_hi + base)     = __nv_bfloat162(h[0], h[1]);
    *(__nv_bfloat162*)(g_xn_hi + base + 2) = __nv_bfloat162(h[2], h[3]);
    *(__nv_bfloat162*)(g_xn_lo + base)     = __nv_bfloat162(l[0], l[1]);
    *(__nv_bfloat162*)(g_xn_lo + base + 2) = __nv_bfloat162(l[2], l[3]);
}

// ============ bf16 split-GEMM (unchanged from round 6) ============
#define PLANE_U32 (128 * 8)
#define STAGE_U32 (4 * PLANE_U32)
#define GEMM_SMEM (3 * STAGE_U32 * 4)

template <int WHICH>
__global__ void __launch_bounds__(256, 2) gemm_bf(const float* __restrict__ R,
                                                  float* __restrict__ Cout) {
    constexpr int NTOT = (WHICH == 1) ? 2 * DI : Dd;
    constexpr int KK   = (WHICH == 1) ? Dd : DI;
    constexpr bool RESADD = (WHICH == 2);
    const __nv_bfloat16* Ah = (WHICH == 1) ? g_xn_hi : g_act_hi;
    const __nv_bfloat16* Al = (WHICH == 1) ? g_xn_lo : g_act_lo;
    const __nv_bfloat16* Wh = (WHICH == 1) ? g_w1_hi : g_w2_hi;
    const __nv_bfloat16* Wl = (WHICH == 1) ? g_w1_lo : g_w2_lo;
    float* C = (WHICH == 1) ? g_xz : Cout;

    extern __shared__ uint32_t sm[];
    uint32_t sb = smem_u32(sm);
    int tid = threadIdx.x, lane = tid & 31, wid = tid >> 5;
    int wm = wid & 3, wn = wid >> 2;
    int bm = blockIdx.y * 128, bn = blockIdx.x * 128;
    int lr = lane >> 2, lc = lane & 3;

    int r = tid >> 1, half = tid & 1;
    const __nv_bfloat16* pAh = Ah + (size_t)(bm + r) * KK + half * 8;
    const __nv_bfloat16* pAl = Al + (size_t)(bm + r) * KK + half * 8;
    const __nv_bfloat16* pBh = Wh + (size_t)(bn + r) * KK + half * 8;
    const __nv_bfloat16* pBl = Wl + (size_t)(bn + r) * KK + half * 8;
    uint32_t dword = (uint32_t)(r * 8 + (((half << 2) ^ (r & 4)) & 7));
    uint32_t dAh = sb + dword * 4;
    uint32_t dAl = dAh + PLANE_U32 * 4;
    uint32_t dBh = dAh + 2 * PLANE_U32 * 4;
    uint32_t dBl = dAh + 3 * PLANE_U32 * 4;

    const int NIT = KK / 16;
    #define ISSUE(s, k0) do {                          \
        cp16(dAh + (s) * STAGE_U32 * 4, pAh + (k0));   \
        cp16(dAl + (s) * STAGE_U32 * 4, pAl + (k0));   \
        cp16(dBh + (s) * STAGE_U32 * 4, pBh + (k0));   \
        cp16(dBl + (s) * STAGE_U32 * 4, pBl + (k0));   \
        cp_commit();                                   \
    } while (0)

    ISSUE(0, 0);
    ISSUE(1, 16);

    float acc[2][8][4];
    #pragma unroll
    for (int mt = 0; mt < 2; mt++)
        #pragma unroll
        for (int nt = 0; nt < 8; nt++)
            #pragma unroll
            for (int q = 0; q < 4; q++) acc[mt][nt][q] = 0.f;

    for (int i = 0; i < NIT; i++) {
        int s = i % 3;
        if (i + 1 < NIT) cp_wait<1>(); else cp_wait<0>();
        __syncthreads();
        if (i + 2 < NIT) ISSUE((i + 2) % 3, (i + 2) * 16);

        const uint32_t* Sh = sm + s * STAGE_U32;
        const uint32_t* Sl = Sh + PLANE_U32;
        const uint32_t* Th = Sh + 2 * PLANE_U32;
        const uint32_t* Tl = Sh + 3 * PLANE_U32;

        uint32_t ah[2][4], al[2][4];
        #pragma unroll
        for (int mt = 0; mt < 2; mt++) {
            int ar0 = wm * 32 + mt * 16 + lr, ar1 = ar0 + 8;
            int w0 = lc ^ (ar0 & 4);
            int w1 = (lc + 4) ^ (ar0 & 4);
            ah[mt][0] = Sh[ar0 * 8 + w0]; ah[mt][1] = Sh[ar1 * 8 + w0];
            ah[mt][2] = Sh[ar0 * 8 + w1]; ah[mt][3] = Sh[ar1 * 8 + w1];
            al[mt][0] = Sl[ar0 * 8 + w0]; al[mt][1] = Sl[ar1 * 8 + w0];
            al[mt][2] = Sl[ar0 * 8 + w1]; al[mt][3] = Sl[ar1 * 8 + w1];
        }
        #pragma unroll
        for (int nt = 0; nt < 8; nt++) {
            int br = wn * 64 + nt * 8 + lr;
            int w0 = lc ^ (br & 4);
            int w1 = (lc + 4) ^ (br & 4);
            uint32_t bh[2] = { Th[br * 8 + w0], Th[br * 8 + w1] };
            uint32_t bl[2] = { Tl[br * 8 + w0], Tl[br * 8 + w1] };
            #pragma unroll
            for (int mt = 0; mt < 2; mt++) {
                mma_bf16(acc[mt][nt], ah[mt], bh);
                mma_bf16(acc[mt][nt], al[mt], bh);
                mma_bf16(acc[mt][nt], ah[mt], bl);
            }
        }
    }
    #undef ISSUE

    #pragma unroll
    for (int mt = 0; mt < 2; mt++) {
        int m0 = bm + wm * 32 + mt * 16 + lr;
        #pragma unroll
        for (int nt = 0; nt < 8; nt++) {
            int n = bn + wn * 64 + nt * 8 + lc * 2;
            float* C0 = C + (size_t)m0 * NTOT + n;
            float* C1 = C + (size_t)(m0 + 8) * NTOT + n;
            float2 v0 = make_float2(acc[mt][nt][0], acc[mt][nt][1]);
            float2 v1 = make_float2(acc[mt][nt][2], acc[mt][nt][3]);
            if (RESADD) {
                const float2 r0 = *(const float2*)(R + (size_t)m0 * NTOT + n);
                const float2 r1 = *(const float2*)(R + (size_t)(m0 + 8) * NTOT + n);
                v0.x += r0.x; v0.y += r0.y;
                v1.x += r1.x; v1.y += r1.y;
            }
            *(float2*)C0 = v0;
            *(float2*)C1 = v1;
        }
    }
}

// ======== chunked parallel scan: y_t = alpha*y_{t-1} + conv(x)_t ========
// idx -> (b, j, c), c fastest (coalesced). Chunk j covers t in [j*CL, (j+1)*CL).

// Pass 1: zero-init local scan; store end value e_j.
__global__ void __launch_bounds__(256) scan_p1(const float* __restrict__ conv_w,
                                               const float* __restrict__ conv_b,
                                               const float* __restrict__ log_alpha) {
    int idx = blockIdx.x * 256 + threadIdx.x;          // 0 .. Bb*NC*DI-1
    int c = idx & (DI - 1);
    int j = (idx >> 11) & (NC - 1);
    int b = idx >> 17;
    float w0 = conv_w[c * 4 + 0], w1 = conv_w[c * 4 + 1];
    float w2 = conv_w[c * 4 + 2], w3 = conv_w[c * 4 + 3];
    float bias = conv_b[c];
    float alpha = 1.f / (1.f + __expf(-log_alpha[c / HD]));

    const float* xp = g_xz + (size_t)b * Ss * (2 * DI) + c;
    int t0 = j * CL;
    float h0 = (t0 >= 3) ? xp[(size_t)(t0 - 3) * (2 * DI)] : 0.f;
    float h1 = (t0 >= 2) ? xp[(size_t)(t0 - 2) * (2 * DI)] : 0.f;
    float h2 = (t0 >= 1) ? xp[(size_t)(t0 - 1) * (2 * DI)] : 0.f;

    float e = 0.f;
    #pragma unroll 4
    for (int t = t0; t < t0 + CL; t++) {
        float xt = xp[(size_t)t * (2 * DI)];
        float cv = fmaf(w0, h0, fmaf(w1, h1, fmaf(w2, h2, fmaf(w3, xt, bias))));
        h0 = h1; h1 = h2; h2 = xt;
        e = fmaf(alpha, e, cv);
    }
    g_e[idx] = e;
}

// Pass 2: serial prefix over chunks (one thread per (b,c)).
__global__ void __launch_bounds__(256) scan_p2(const float* __restrict__ log_alpha) {
    int idx = blockIdx.x * 256 + threadIdx.x;          // 0 .. Bb*DI-1
    int c = idx & (DI - 1);
    int b = idx >> 11;
    float alpha = 1.f / (1.f + __expf(-log_alpha[c / HD]));
    float aL = powf(alpha, (float)CL);
    float s = 0.f;
    size_t base = (size_t)b * NC * DI + c;
    #pragma unroll 8
    for (int j = 0; j < NC; j++) {
        g_s[base + (size_t)j * DI] = s;
        s = fmaf(aL, s, g_e[base + (size_t)j * DI]);
    }
}

// Pass 3: re-scan with true init state, SiLU*gate, write bf16 hi/lo.
__global__ void __launch_bounds__(256) scan_p3(const float* __restrict__ conv_w,
                                               const float* __restrict__ conv_b,
                                               const float* __restrict__ log_alpha) {
    int idx = blockIdx.x * 256 + threadIdx.x;
    int c = idx & (DI - 1);
    int j = (idx >> 11) & (NC - 1);
    int b = idx >> 17;
    float w0 = conv_w[c * 4 + 0], w1 = conv_w[c * 4 + 1];
    float w2 = conv_w[c * 4 + 2], w3 = conv_w[c * 4 + 3];
    float bias = conv_b[c];
    float alpha = 1.f / (1.f + __expf(-log_alpha[c / HD]));

    const float* xp = g_xz + (size_t)b * Ss * (2 * DI) + c;
    const float* gp = xp + DI;
    size_t ao = (size_t)b * Ss * DI + c;
    int t0 = j * CL;
    float h0 = (t0 >= 3) ? xp[(size_t)(t0 - 3) * (2 * DI)] : 0.f;
    float h1 = (t0 >= 2) ? xp[(size_t)(t0 - 2) * (2 * DI)] : 0.f;
    float h2 = (t0 >= 1) ? xp[(size_t)(t0 - 1) * (2 * DI)] : 0.f;

    float y = g_s[idx];
    #pragma unroll 4
    for (int t = t0; t < t0 + CL; t++) {
        float xt = xp[(size_t)t * (2 * DI)];
        float g  = gp[(size_t)t * (2 * DI)];
        float cv = fmaf(w0, h0, fmaf(w1, h1, fmaf(w2, h2, fmaf(w3, xt, bias))));
        h0 = h1; h1 = h2; h2 = xt;
        y = fmaf(alpha, y, cv);
        float sl = y * (1.f / (1.f + __expf(-y)));
        float v = sl * g;
        __nv_bfloat16 hh, ll;
        bsplit(v, hh, ll);
        g_act_hi[ao + (size_t)t * DI] = hh;
        g_act_lo[ao + (size_t)t * DI] = ll;
    }
}

// ---------------- launch (NO device-symbol references in host code) ----------------
extern "C" void kernel_launch(void* const* d_in, const int* in_sizes, int n_in,
                              void* d_out, int out_size) {
    const float* x          = (const float*)d_in[0];
    const float* norm_w     = (const float*)d_in[1];
    const float* norm_b     = (const float*)d_in[2];
    const float* in_proj_w  = (const float*)d_in[3];
    const float* conv_w     = (const float*)d_in[4];
    const float* conv_b     = (const float*)d_in[5];
    const float* out_proj_w = (const float*)d_in[6];
    const float* log_alpha  = (const float*)d_in[7];
    float* out = (float*)d_out;

    cudaFuncSetAttribute(gemm_bf<1>, cudaFuncAttributeMaxDynamicSharedMemorySize, GEMM_SMEM);
    cudaFuncSetAttribute(gemm_bf<2>, cudaFuncAttributeMaxDynamicSharedMemorySize, GEMM_SMEM);

    int n1 = 2 * DI * Dd / 4, n2 = Dd * DI / 4;
    wprep<1><<<(n1 + 255) / 256, 256>>>(in_proj_w);
    wprep<2><<<(n2 + 255) / 256, 256>>>(out_proj_w);

    ln_kernel<<<Mm, 256>>>(x, norm_w, norm_b);

    dim3 g1((2 * DI) / 128, Mm / 128);           // (32, 128)
    gemm_bf<1><<<g1, 256, GEMM_SMEM>>>(nullptr, nullptr);

    scan_p1<<<(Bb * NC * DI) / 256, 256>>>(conv_w, conv_b, log_alpha);
    scan_p2<<<(Bb * DI) / 256, 256>>>(log_alpha);
    scan_p3<<<(Bb * NC * DI) / 256, 256>>>(conv_w, conv_b, log_alpha);

    dim3 g2(Dd / 128, Mm / 128);                 // (8, 128)
    gemm_bf<2><<<g2, 256, GEMM_SMEM>>>(x, out);
}

// round 8
// speedup vs baseline: 3.8534x; 1.0500x over previous
#include <cuda_runtime.h>
#include <cuda_bf16.h>
#include <math.h>
#include <stdint.h>

#define Bb 4
#define Ss 4096
#define Dd 1024
#define DI 2048
#define HD 256
#define Mm (Bb * Ss)   // 16384 tokens
#define CL 64          // scan chunk length
#define NC (Ss / CL)   // 64 chunks

// ---------------- scratch (device-code references ONLY; never named in host code) ----
__device__ float g_xz[(size_t)Mm * 2 * DI];      // 256 MB (gemm1 out, fp32)
__device__ float g_xn[(size_t)Mm * Dd];          //  64 MB (LN out, tf32-rounded)
__device__ float g_act[(size_t)Mm * DI];         // 128 MB (scan out, tf32-rounded)
__device__ float g_w1[(size_t)2 * DI * Dd];      //  32 MB (in_proj, tf32-rounded)
__device__ float g_w2[(size_t)Dd * DI];          //   8 MB (out_proj, tf32-rounded)
__device__ float g_e[(size_t)Bb * NC * DI];      //   2 MB (chunk end values)
__device__ float g_s[(size_t)Bb * NC * DI];      //   2 MB (chunk init states)

// ================= helpers =================
__device__ __forceinline__ uint32_t smem_u32(const void* p) {
    uint32_t a;
    asm("{ .reg .u64 t; cvta.to.shared.u64 t, %1; cvt.u32.u64 %0, t; }" : "=r"(a) : "l"(p));
    return a;
}
__device__ __forceinline__ float tf32r(float x) {
    float r; asm("cvt.rna.tf32.f32 %0, %1;" : "=f"(r) : "f"(x)); return r;
}
__device__ __forceinline__ void cp16(uint32_t dst, const void* src) {
    asm volatile("cp.async.cg.shared.global [%0], [%1], 16;" :: "r"(dst), "l"(src));
}
__device__ __forceinline__ void cp_commit() { asm volatile("cp.async.commit_group;" ::: "memory"); }
template <int N> __device__ __forceinline__ void cp_wait() {
    asm volatile("cp.async.wait_group %0;" :: "n"(N) : "memory");
}
// tf32 m16n8k8: d(f32) += a(tf32 x4) * b(tf32 x2)
__device__ __forceinline__ void mma_tf32(float* d, const float* a, const float* b) {
    asm volatile(
        "mma.sync.aligned.m16n8k8.row.col.f32.tf32.tf32.f32 "
        "{%0,%1,%2,%3}, {%4,%5,%6,%7}, {%8,%9}, {%0,%1,%2,%3};"
        : "+f"(d[0]), "+f"(d[1]), "+f"(d[2]), "+f"(d[3])
        : "r"(__float_as_uint(a[0])), "r"(__float_as_uint(a[1])),
          "r"(__float_as_uint(a[2])), "r"(__float_as_uint(a[3])),
          "r"(__float_as_uint(b[0])), "r"(__float_as_uint(b[1])));
}

// ---------------- weight round to tf32 (globals chosen in DEVICE code) --------
template <int WHICH>
__global__ void __launch_bounds__(256) wprep(const float* __restrict__ s) {
    float* d = (WHICH == 1) ? g_w1 : g_w2;
    const int n4 = (WHICH == 1) ? (2 * DI * Dd / 4) : (Dd * DI / 4);
    int i = blockIdx.x * 256 + threadIdx.x;
    if (i < n4) {
        float4 v = ((const float4*)s)[i];
        v.x = tf32r(v.x); v.y = tf32r(v.y); v.z = tf32r(v.z); v.w = tf32r(v.w);
        ((float4*)d)[i] = v;
    }
}

// ---------------- LayerNorm (writes tf32-rounded fp32) ----------------
__global__ void __launch_bounds__(256) ln_kernel(const float* __restrict__ x,
                                                 const float* __restrict__ w,
                                                 const float* __restrict__ bia) {
    int m = blockIdx.x;
    int t = threadIdx.x;
    const float4* xr = (const float4*)(x + (size_t)m * Dd);
    float4 xv = xr[t];
    float s  = xv.x + xv.y + xv.z + xv.w;
    float s2 = xv.x * xv.x + xv.y * xv.y + xv.z * xv.z + xv.w * xv.w;
    #pragma unroll
    for (int o = 16; o; o >>= 1) {
        s  += __shfl_xor_sync(0xffffffffu, s, o);
        s2 += __shfl_xor_sync(0xffffffffu, s2, o);
    }
    __shared__ float shs[8], shs2[8];
    int wid = t >> 5, lane = t & 31;
    if (lane == 0) { shs[wid] = s; shs2[wid] = s2; }
    __syncthreads();
    s = 0.f; s2 = 0.f;
    #pragma unroll
    for (int i = 0; i < 8; i++) { s += shs[i]; s2 += shs2[i]; }
    float mu  = s * (1.0f / Dd);
    float var = s2 * (1.0f / Dd) - mu * mu;
    float rstd = rsqrtf(var + 1e-5f);
    float4 wv = ((const float4*)w)[t];
    float4 bv = ((const float4*)bia)[t];
    float4 o;
    o.x = tf32r((xv.x - mu) * rstd * wv.x + bv.x);
    o.y = tf32r((xv.y - mu) * rstd * wv.y + bv.y);
    o.z = tf32r((xv.z - mu) * rstd * wv.z + bv.z);
    o.w = tf32r((xv.w - mu) * rstd * wv.w + bv.w);
    ((float4*)(g_xn + (size_t)m * Dd))[t] = o;
}

// ============ tf32 single-pass GEMM: C[m,n] = sum_k A[m,k]*W[n,k] (+res) ============
// Block 128x128, BK=16, 3-stage cp.async pipeline, 8 warps (4m x 2n), warp 32x64.
// smem stride 20 floats: conflict-free STS.128 and m16n8k8 fragment LDS.
#define AST 20
#define STG_F (128 * AST)                  // floats per stage plane (A or B)
#define GEMM_SMEM (6 * STG_F * 4)          // 61440 B: 3 A stages + 3 B stages

template <int WHICH>                        // 1: xn @ w1 -> g_xz ; 2: act @ w2 + R -> Cout
__global__ void __launch_bounds__(256, 2) gemm_tf(const float* __restrict__ R,
                                                  float* __restrict__ Cout) {
    constexpr int NTOT = (WHICH == 1) ? 2 * DI : Dd;
    constexpr int KK   = (WHICH == 1) ? Dd : DI;
    constexpr bool RESADD = (WHICH == 2);
    const float* A = (WHICH == 1) ? g_xn : g_act;
    const float* W = (WHICH == 1) ? g_w1 : g_w2;
    float* C = (WHICH == 1) ? g_xz : Cout;

    extern __shared__ float sm[];
    uint32_t sb = smem_u32(sm);
    int tid = threadIdx.x, lane = tid & 31, wid = tid >> 5;
    int wm = wid & 3, wn = wid >> 2;
    int bm = blockIdx.y * 128, bn = blockIdx.x * 128;
    int lr = lane >> 2, lc = lane & 3;

    // producer coords: row r (0..127), two adjacent 16B chunks h2, h2+1
    int r = tid >> 1, h2 = (tid & 1) * 2;
    const float* pA = A + (size_t)(bm + r) * KK + h2 * 4;
    const float* pB = W + (size_t)(bn + r) * KK + h2 * 4;
    uint32_t dA = sb + (uint32_t)(r * AST + h2 * 4) * 4;
    uint32_t dB = dA + 3 * STG_F * 4;

    const int NIT = KK / 16;
    #define ISSUE(s, k0) do {                        \
        cp16(dA + (s) * STG_F * 4,      pA + (k0));  \
        cp16(dA + (s) * STG_F * 4 + 16, pA + (k0) + 4); \
        cp16(dB + (s) * STG_F * 4,      pB + (k0));  \
        cp16(dB + (s) * STG_F * 4 + 16, pB + (k0) + 4); \
        cp_commit();                                 \
    } while (0)

    ISSUE(0, 0);
    ISSUE(1, 16);

    float acc[2][8][4];
    #pragma unroll
    for (int mt = 0; mt < 2; mt++)
        #pragma unroll
        for (int nt = 0; nt < 8; nt++)
            #pragma unroll
            for (int q = 0; q < 4; q++) acc[mt][nt][q] = 0.f;

    for (int i = 0; i < NIT; i++) {
        int s = i % 3;
        if (i + 1 < NIT) cp_wait<1>(); else cp_wait<0>();
        __syncthreads();
        if (i + 2 < NIT) ISSUE((i + 2) % 3, (i + 2) * 16);

        const float* As = sm + s * STG_F;
        const float* Bs = sm + (3 + s) * STG_F;
        #pragma unroll
        for (int ks = 0; ks < 2; ks++) {
            int kc = ks * 8 + lc;
            float a[2][4];
            #pragma unroll
            for (int mt = 0; mt < 2; mt++) {
                int ar = wm * 32 + mt * 16 + lr;
                a[mt][0] = As[ar * AST + kc];
                a[mt][1] = As[(ar + 8) * AST + kc];
                a[mt][2] = As[ar * AST + kc + 4];
                a[mt][3] = As[(ar + 8) * AST + kc + 4];
            }
            float b[8][2];
            #pragma unroll
            for (int nt = 0; nt < 8; nt++) {
                int br = wn * 64 + nt * 8 + lr;
                b[nt][0] = Bs[br * AST + kc];
                b[nt][1] = Bs[br * AST + kc + 4];
            }
            #pragma unroll
            for (int mt = 0; mt < 2; mt++)
                #pragma unroll
                for (int nt = 0; nt < 8; nt++)
                    mma_tf32(acc[mt][nt], a[mt], b[nt]);
        }
    }
    #undef ISSUE

    // epilogue
    #pragma unroll
    for (int mt = 0; mt < 2; mt++) {
        int m0 = bm + wm * 32 + mt * 16 + lr;
        #pragma unroll
        for (int nt = 0; nt < 8; nt++) {
            int n = bn + wn * 64 + nt * 8 + lc * 2;
            float* C0 = C + (size_t)m0 * NTOT + n;
            float* C1 = C + (size_t)(m0 + 8) * NTOT + n;
            float2 v0 = make_float2(acc[mt][nt][0], acc[mt][nt][1]);
            float2 v1 = make_float2(acc[mt][nt][2], acc[mt][nt][3]);
            if (RESADD) {
                const float2 r0 = *(const float2*)(R + (size_t)m0 * NTOT + n);
                const float2 r1 = *(const float2*)(R + (size_t)(m0 + 8) * NTOT + n);
                v0.x += r0.x; v0.y += r0.y;
                v1.x += r1.x; v1.y += r1.y;
            }
            *(float2*)C0 = v0;
            *(float2*)C1 = v1;
        }
    }
}

// ======== chunked parallel scan: y_t = alpha*y_{t-1} + conv(x)_t ========
// Pass 1: zero-init local scan; store end value e_j.
__global__ void __launch_bounds__(256) scan_p1(const float* __restrict__ conv_w,
                                               const float* __restrict__ conv_b,
                                               const float* __restrict__ log_alpha) {
    int idx = blockIdx.x * 256 + threadIdx.x;
    int c = idx & (DI - 1);
    int j = (idx >> 11) & (NC - 1);
    int b = idx >> 17;
    float w0 = conv_w[c * 4 + 0], w1 = conv_w[c * 4 + 1];
    float w2 = conv_w[c * 4 + 2], w3 = conv_w[c * 4 + 3];
    float bias = conv_b[c];
    float alpha = 1.f / (1.f + __expf(-log_alpha[c / HD]));

    const float* xp = g_xz + (size_t)b * Ss * (2 * DI) + c;
    int t0 = j * CL;
    float h0 = (t0 >= 3) ? xp[(size_t)(t0 - 3) * (2 * DI)] : 0.f;
    float h1 = (t0 >= 2) ? xp[(size_t)(t0 - 2) * (2 * DI)] : 0.f;
    float h2 = (t0 >= 1) ? xp[(size_t)(t0 - 1) * (2 * DI)] : 0.f;

    float e = 0.f;
    #pragma unroll 4
    for (int t = t0; t < t0 + CL; t++) {
        float xt = xp[(size_t)t * (2 * DI)];
        float cv = fmaf(w0, h0, fmaf(w1, h1, fmaf(w2, h2, fmaf(w3, xt, bias))));
        h0 = h1; h1 = h2; h2 = xt;
        e = fmaf(alpha, e, cv);
    }
    g_e[idx] = e;
}

// Pass 2: serial prefix over chunk carries (one thread per (b,c)).
__global__ void __launch_bounds__(256) scan_p2(const float* __restrict__ log_alpha) {
    int idx = blockIdx.x * 256 + threadIdx.x;
    int c = idx & (DI - 1);
    int b = idx >> 11;
    float alpha = 1.f / (1.f + __expf(-log_alpha[c / HD]));
    float aL = powf(alpha, (float)CL);
    float s = 0.f;
    size_t base = (size_t)b * NC * DI + c;
    #pragma unroll 8
    for (int j = 0; j < NC; j++) {
        g_s[base + (size_t)j * DI] = s;
        s = fmaf(aL, s, g_e[base + (size_t)j * DI]);
    }
}

// Pass 3: re-scan with true init state, SiLU*gate, write tf32-rounded fp32.
__global__ void __launch_bounds__(256) scan_p3(const float* __restrict__ conv_w,
                                               const float* __restrict__ conv_b,
                                               const float* __restrict__ log_alpha) {
    int idx = blockIdx.x * 256 + threadIdx.x;
    int c = idx & (DI - 1);
    int j = (idx >> 11) & (NC - 1);
    int b = idx >> 17;
    float w0 = conv_w[c * 4 + 0], w1 = conv_w[c * 4 + 1];
    float w2 = conv_w[c * 4 + 2], w3 = conv_w[c * 4 + 3];
    float bias = conv_b[c];
    float alpha = 1.f / (1.f + __expf(-log_alpha[c / HD]));

    const float* xp = g_xz + (size_t)b * Ss * (2 * DI) + c;
    const float* gp = xp + DI;
    size_t ao = (size_t)b * Ss * DI + c;
    int t0 = j * CL;
    float h0 = (t0 >= 3) ? xp[(size_t)(t0 - 3) * (2 * DI)] : 0.f;
    float h1 = (t0 >= 2) ? xp[(size_t)(t0 - 2) * (2 * DI)] : 0.f;
    float h2 = (t0 >= 1) ? xp[(size_t)(t0 - 1) * (2 * DI)] : 0.f;

    float y = g_s[idx];
    #pragma unroll 4
    for (int t = t0; t < t0 + CL; t++) {
        float xt = xp[(size_t)t * (2 * DI)];
        float g  = gp[(size_t)t * (2 * DI)];
        float cv = fmaf(w0, h0, fmaf(w1, h1, fmaf(w2, h2, fmaf(w3, xt, bias))));
        h0 = h1; h1 = h2; h2 = xt;
        y = fmaf(alpha, y, cv);
        float sl = y * (1.f / (1.f + __expf(-y)));
        g_act[ao + (size_t)t * DI] = tf32r(sl * g);
    }
}

// ---------------- launch (NO device-symbol references in host code) ----------------
extern "C" void kernel_launch(void* const* d_in, const int* in_sizes, int n_in,
                              void* d_out, int out_size) {
    const float* x          = (const float*)d_in[0];
    const float* norm_w     = (const float*)d_in[1];
    const float* norm_b     = (const float*)d_in[2];
    const float* in_proj_w  = (const float*)d_in[3];
    const float* conv_w     = (const float*)d_in[4];
    const float* conv_b     = (const float*)d_in[5];
    const float* out_proj_w = (const float*)d_in[6];
    const float* log_alpha  = (const float*)d_in[7];
    float* out = (float*)d_out;

    cudaFuncSetAttribute(gemm_tf<1>, cudaFuncAttributeMaxDynamicSharedMemorySize, GEMM_SMEM);
    cudaFuncSetAttribute(gemm_tf<2>, cudaFuncAttributeMaxDynamicSharedMemorySize, GEMM_SMEM);

    int n1 = 2 * DI * Dd / 4, n2 = Dd * DI / 4;
    wprep<1><<<(n1 + 255) / 256, 256>>>(in_proj_w);
    wprep<2><<<(n2 + 255) / 256, 256>>>(out_proj_w);

    ln_kernel<<<Mm, 256>>>(x, norm_w, norm_b);

    dim3 g1((2 * DI) / 128, Mm / 128);           // (32, 128)
    gemm_tf<1><<<g1, 256, GEMM_SMEM>>>(nullptr, nullptr);

    scan_p1<<<(Bb * NC * DI) / 256, 256>>>(conv_w, conv_b, log_alpha);
    scan_p2<<<(Bb * DI) / 256, 256>>>(log_alpha);
    scan_p3<<<(Bb * NC * DI) / 256, 256>>>(conv_w, conv_b, log_alpha);

    dim3 g2(Dd / 128, Mm / 128);                 // (8, 128)
    gemm_tf<2><<<g2, 256, GEMM_SMEM>>>(x, out);
}

// round 9
// speedup vs baseline: 4.8126x; 1.2489x over previous
#include <cuda_runtime.h>
#include <cuda_fp16.h>
#include <math.h>
#include <stdint.h>

#define Bb 4
#define Ss 4096
#define Dd 1024
#define DI 2048
#define HD 256
#define Mm (Bb * Ss)   // 16384 tokens
#define CL 64          // scan chunk length
#define NC (Ss / CL)   // 64 chunks

// ---------------- scratch (device-code references ONLY; never named in host code) ----
__device__ float g_xz[(size_t)Mm * 2 * DI];      // 256 MB (gemm1 out, fp32)
__device__ __half g_xnh[(size_t)Mm * Dd];        //  32 MB (LN out hi)
__device__ __half g_xnl[(size_t)Mm * Dd];        //  32 MB (LN out lo)
__device__ __half g_acth[(size_t)Mm * DI];       //  64 MB (scan out hi)
__device__ __half g_actl[(size_t)Mm * DI];       //  64 MB (scan out lo)
__device__ __half g_w1h[(size_t)2 * DI * Dd];    //   8 MB (in_proj fp16)
__device__ __half g_w2h[(size_t)Dd * DI];        //   4 MB (out_proj fp16)
__device__ float g_e[(size_t)Bb * NC * DI];      //   2 MB (chunk end values)
__device__ float g_s[(size_t)Bb * NC * DI];      //   2 MB (chunk init states)

// ================= helpers =================
__device__ __forceinline__ uint32_t smem_u32(const void* p) {
    uint32_t a;
    asm("{ .reg .u64 t; cvta.to.shared.u64 t, %1; cvt.u32.u64 %0, t; }" : "=r"(a) : "l"(p));
    return a;
}
__device__ __forceinline__ void hsplit(float x, __half& h, __half& l) {
    h = __float2half_rn(x);
    l = __float2half_rn(x - __half2float(h));
}
__device__ __forceinline__ void cp16(uint32_t dst, const void* src) {
    asm volatile("cp.async.cg.shared.global [%0], [%1], 16;" :: "r"(dst), "l"(src));
}
__device__ __forceinline__ void cp_commit() { asm volatile("cp.async.commit_group;" ::: "memory"); }
template <int N> __device__ __forceinline__ void cp_wait() {
    asm volatile("cp.async.wait_group %0;" :: "n"(N) : "memory");
}
__device__ __forceinline__ void ldsm4(uint32_t& r0, uint32_t& r1, uint32_t& r2, uint32_t& r3,
                                      uint32_t addr) {
    asm volatile("ldmatrix.sync.aligned.m8n8.x4.shared.b16 {%0,%1,%2,%3}, [%4];"
                 : "=r"(r0), "=r"(r1), "=r"(r2), "=r"(r3) : "r"(addr));
}
// f16 m16n8k16: d(f32) += a(f16x2 x4) * b(f16x2 x2)
__device__ __forceinline__ void mma_f16(float* d, const uint32_t* a, const uint32_t* b) {
    asm volatile(
        "mma.sync.aligned.m16n8k16.row.col.f32.f16.f16.f32 "
        "{%0,%1,%2,%3}, {%4,%5,%6,%7}, {%8,%9}, {%0,%1,%2,%3};"
        : "+f"(d[0]), "+f"(d[1]), "+f"(d[2]), "+f"(d[3])
        : "r"(a[0]), "r"(a[1]), "r"(a[2]), "r"(a[3]), "r"(b[0]), "r"(b[1]));
}

// ---------------- weight round to fp16 (globals chosen in DEVICE code) --------
template <int WHICH>
__global__ void __launch_bounds__(256) wprep(const float* __restrict__ s) {
    __half* d = (WHICH == 1) ? g_w1h : g_w2h;
    const int n4 = (WHICH == 1) ? (2 * DI * Dd / 4) : (Dd * DI / 4);
    int i = blockIdx.x * 256 + threadIdx.x;
    if (i < n4) {
        float4 v = ((const float4*)s)[i];
        __half2 p0 = __halves2half2(__float2half_rn(v.x), __float2half_rn(v.y));
        __half2 p1 = __halves2half2(__float2half_rn(v.z), __float2half_rn(v.w));
        *(__half2*)(d + (size_t)i * 4)     = p0;
        *(__half2*)(d + (size_t)i * 4 + 2) = p1;
    }
}

// ---------------- LayerNorm (writes fp16 hi/lo planes, exact split) ----------------
__global__ void __launch_bounds__(256) ln_kernel(const float* __restrict__ x,
                                                 const float* __restrict__ w,
                                                 const float* __restrict__ bia) {
    int m = blockIdx.x;
    int t = threadIdx.x;
    const float4* xr = (const float4*)(x + (size_t)m * Dd);
    float4 xv = xr[t];
    float s  = xv.x + xv.y + xv.z + xv.w;
    float s2 = xv.x * xv.x + xv.y * xv.y + xv.z * xv.z + xv.w * xv.w;
    #pragma unroll
    for (int o = 16; o; o >>= 1) {
        s  += __shfl_xor_sync(0xffffffffu, s, o);
        s2 += __shfl_xor_sync(0xffffffffu, s2, o);
    }
    __shared__ float shs[8], shs2[8];
    int wid = t >> 5, lane = t & 31;
    if (lane == 0) { shs[wid] = s; shs2[wid] = s2; }
    __syncthreads();
    s = 0.f; s2 = 0.f;
    #pragma unroll
    for (int i = 0; i < 8; i++) { s += shs[i]; s2 += shs2[i]; }
    float mu  = s * (1.0f / Dd);
    float var = s2 * (1.0f / Dd) - mu * mu;
    float rstd = rsqrtf(var + 1e-5f);
    float4 wv = ((const float4*)w)[t];
    float4 bv = ((const float4*)bia)[t];
    float o0 = (xv.x - mu) * rstd * wv.x + bv.x;
    float o1 = (xv.y - mu) * rstd * wv.y + bv.y;
    float o2 = (xv.z - mu) * rstd * wv.z + bv.z;
    float o3 = (xv.w - mu) * rstd * wv.w + bv.w;
    __half h[4], l[4];
    hsplit(o0, h[0], l[0]); hsplit(o1, h[1], l[1]);
    hsplit(o2, h[2], l[2]); hsplit(o3, h[3], l[3]);
    size_t base = (size_t)m * Dd + 4 * t;
    *(__half2*)(g_xnh + base)     = __halves2half2(h[0], h[1]);
    *(__half2*)(g_xnh + base + 2) = __halves2half2(h[2], h[3]);
    *(__half2*)(g_xnl + base)     = __halves2half2(l[0], l[1]);
    *(__half2*)(g_xnl + base + 2) = __halves2half2(l[2], l[3]);
}

// ============ fp16 2-pass split GEMM: C[m,n] = sum_k A[m,k]*W[n,k] (+res) ============
// Block 128x128, BK=32, 3-stage cp.async pipeline, 8 warps (4m x 2n), warp 32x64.
// smem: per stage 3 planes (A_hi, A_lo, W) of 128 rows x 40 halfs (pad 8) = 10240 B.
// ldmatrix.x4 fragment loads; 80B row stride -> conflict-free 8-row LDSM phases,
// all addresses 16B aligned (80 = 16*5).
#define HST 40
#define PLANE_B (128 * HST * 2)            // 10240
#define STAGE_B (3 * PLANE_B)              // 30720
#define GEMM_SMEM (3 * STAGE_B)            // 92160

template <int WHICH>                        // 1: xn @ w1 -> g_xz ; 2: act @ w2 + R -> Cout
__global__ void __launch_bounds__(256, 2) gemm_h(const float* __restrict__ R,
                                                 float* __restrict__ Cout) {
    constexpr int NTOT = (WHICH == 1) ? 2 * DI : Dd;
    constexpr int KK   = (WHICH == 1) ? Dd : DI;
    constexpr bool RESADD = (WHICH == 2);
    const __half* Ah = (WHICH == 1) ? g_xnh : g_acth;
    const __half* Al = (WHICH == 1) ? g_xnl : g_actl;
    const __half* Wp = (WHICH == 1) ? g_w1h : g_w2h;
    float* C = (WHICH == 1) ? g_xz : Cout;

    extern __shared__ char smraw[];
    uint32_t sb = smem_u32(smraw);
    int tid = threadIdx.x, lane = tid & 31, wid = tid >> 5;
    int wm = wid & 3, wn = wid >> 2;
    int bm = blockIdx.y * 128, bn = blockIdx.x * 128;
    int lr = lane >> 2, lc = lane & 3;

    // producer coords: row r (0..127), 16B chunk pair cpair*8 halfs
    int r = tid >> 1, cp8 = (tid & 1) * 16;    // halfs offset of first chunk
    const __half* pAh = Ah + (size_t)(bm + r) * KK + cp8;
    const __half* pAl = Al + (size_t)(bm + r) * KK + cp8;
    const __half* pW  = Wp + (size_t)(bn + r) * KK + cp8;
    uint32_t dA = sb + (uint32_t)(r * HST + cp8) * 2;
    uint32_t dL = dA + PLANE_B;
    uint32_t dW = dA + 2 * PLANE_B;

    const int NIT = KK / 32;
    #define ISSUE(s, k0) do {                             \
        cp16(dA + (s) * STAGE_B,      pAh + (k0));        \
        cp16(dA + (s) * STAGE_B + 16, pAh + (k0) + 8);    \
        cp16(dL + (s) * STAGE_B,      pAl + (k0));        \
        cp16(dL + (s) * STAGE_B + 16, pAl + (k0) + 8);    \
        cp16(dW + (s) * STAGE_B,      pW  + (k0));        \
        cp16(dW + (s) * STAGE_B + 16, pW  + (k0) + 8);    \
        cp_commit();                                      \
    } while (0)

    ISSUE(0, 0);
    ISSUE(1, 32);

    float acc[2][8][4];
    #pragma unroll
    for (int mt = 0; mt < 2; mt++)
        #pragma unroll
        for (int nt = 0; nt < 8; nt++)
            #pragma unroll
            for (int q = 0; q < 4; q++) acc[mt][nt][q] = 0.f;

    // per-lane LDSM address components (in halfs)
    int arow = lane & 15;                 // m row within 16
    int akoff = (lane >> 4) * 8;          // k halfs offset for tiles 2,3
    int brow = (lane & 7) + ((lane & 16) ? 8 : 0);   // n row within 16
    int bkoff = (lane & 8) ? 8 : 0;       // k halfs offset

    for (int i = 0; i < NIT; i++) {
        int s = i % 3;
        if (i + 1 < NIT) cp_wait<1>(); else cp_wait<0>();
        __syncthreads();
        if (i + 2 < NIT) ISSUE((i + 2) % 3, (i + 2) * 32);

        uint32_t As = sb + s * STAGE_B;
        uint32_t Ls = As + PLANE_B;
        uint32_t Ws = As + 2 * PLANE_B;

        #pragma unroll
        for (int ks = 0; ks < 2; ks++) {
            int k0 = ks * 16;
            uint32_t ah[2][4], al[2][4];
            #pragma unroll
            for (int mt = 0; mt < 2; mt++) {
                uint32_t off = (uint32_t)((wm * 32 + mt * 16 + arow) * HST + k0 + akoff) * 2;
                ldsm4(ah[mt][0], ah[mt][1], ah[mt][2], ah[mt][3], As + off);
                ldsm4(al[mt][0], al[mt][1], al[mt][2], al[mt][3], Ls + off);
            }
            #pragma unroll
            for (int ntp = 0; ntp < 4; ntp++) {
                uint32_t b0, b1, b2, b3;
                uint32_t off = (uint32_t)((wn * 64 + ntp * 16 + brow) * HST + k0 + bkoff) * 2;
                ldsm4(b0, b1, b2, b3, Ws + off);
                uint32_t bA[2] = { b0, b1 };    // nt = 2*ntp
                uint32_t bB[2] = { b2, b3 };    // nt = 2*ntp+1
                #pragma unroll
                for (int mt = 0; mt < 2; mt++) {
                    mma_f16(acc[mt][2 * ntp],     ah[mt], bA);
                    mma_f16(acc[mt][2 * ntp],     al[mt], bA);
                    mma_f16(acc[mt][2 * ntp + 1], ah[mt], bB);
                    mma_f16(acc[mt][2 * ntp + 1], al[mt], bB);
                }
            }
        }
    }
    #undef ISSUE

    // epilogue
    #pragma unroll
    for (int mt = 0; mt < 2; mt++) {
        int m0 = bm + wm * 32 + mt * 16 + lr;
        #pragma unroll
        for (int nt = 0; nt < 8; nt++) {
            int n = bn + wn * 64 + nt * 8 + lc * 2;
            float* C0 = C + (size_t)m0 * NTOT + n;
            float* C1 = C + (size_t)(m0 + 8) * NTOT + n;
            float2 v0 = make_float2(acc[mt][nt][0], acc[mt][nt][1]);
            float2 v1 = make_float2(acc[mt][nt][2], acc[mt][nt][3]);
            if (RESADD) {
                const float2 r0 = *(const float2*)(R + (size_t)m0 * NTOT + n);
                const float2 r1 = *(const float2*)(R + (size_t)(m0 + 8) * NTOT + n);
                v0.x += r0.x; v0.y += r0.y;
                v1.x += r1.x; v1.y += r1.y;
            }
            *(float2*)C0 = v0;
            *(float2*)C1 = v1;
        }
    }
}

// ======== chunked parallel scan: y_t = alpha*y_{t-1} + conv(x)_t ========
__global__ void __launch_bounds__(256) scan_p1(const float* __restrict__ conv_w,
                                               const float* __restrict__ conv_b,
                                               const float* __restrict__ log_alpha) {
    int idx = blockIdx.x * 256 + threadIdx.x;
    int c = idx & (DI - 1);
    int j = (idx >> 11) & (NC - 1);
    int b = idx >> 17;
    float w0 = conv_w[c * 4 + 0], w1 = conv_w[c * 4 + 1];
    float w2 = conv_w[c * 4 + 2], w3 = conv_w[c * 4 + 3];
    float bias = conv_b[c];
    float alpha = 1.f / (1.f + __expf(-log_alpha[c / HD]));

    const float* xp = g_xz + (size_t)b * Ss * (2 * DI) + c;
    int t0 = j * CL;
    float h0 = (t0 >= 3) ? xp[(size_t)(t0 - 3) * (2 * DI)] : 0.f;
    float h1 = (t0 >= 2) ? xp[(size_t)(t0 - 2) * (2 * DI)] : 0.f;
    float h2 = (t0 >= 1) ? xp[(size_t)(t0 - 1) * (2 * DI)] : 0.f;

    float e = 0.f;
    #pragma unroll 4
    for (int t = t0; t < t0 + CL; t++) {
        float xt = xp[(size_t)t * (2 * DI)];
        float cv = fmaf(w0, h0, fmaf(w1, h1, fmaf(w2, h2, fmaf(w3, xt, bias))));
        h0 = h1; h1 = h2; h2 = xt;
        e = fmaf(alpha, e, cv);
    }
    g_e[idx] = e;
}

__global__ void __launch_bounds__(256) scan_p2(const float* __restrict__ log_alpha) {
    int idx = blockIdx.x * 256 + threadIdx.x;
    int c = idx & (DI - 1);
    int b = idx >> 11;
    float alpha = 1.f / (1.f + __expf(-log_alpha[c / HD]));
    float aL = powf(alpha, (float)CL);
    float s = 0.f;
    size_t base = (size_t)b * NC * DI + c;
    #pragma unroll 8
    for (int j = 0; j < NC; j++) {
        g_s[base + (size_t)j * DI] = s;
        s = fmaf(aL, s, g_e[base + (size_t)j * DI]);
    }
}

__global__ void __launch_bounds__(256) scan_p3(const float* __restrict__ conv_w,
                                               const float* __restrict__ conv_b,
                                               const float* __restrict__ log_alpha) {
    int idx = blockIdx.x * 256 + threadIdx.x;
    int c = idx & (DI - 1);
    int j = (idx >> 11) & (NC - 1);
    int b = idx >> 17;
    float w0 = conv_w[c * 4 + 0], w1 = conv_w[c * 4 + 1];
    float w2 = conv_w[c * 4 + 2], w3 = conv_w[c * 4 + 3];
    float bias = conv_b[c];
    float alpha = 1.f / (1.f + __expf(-log_alpha[c / HD]));

    const float* xp = g_xz + (size_t)b * Ss * (2 * DI) + c;
    const float* gp = xp + DI;
    size_t ao = (size_t)b * Ss * DI + c;
    int t0 = j * CL;
    float h0 = (t0 >= 3) ? xp[(size_t)(t0 - 3) * (2 * DI)] : 0.f;
    float h1 = (t0 >= 2) ? xp[(size_t)(t0 - 2) * (2 * DI)] : 0.f;
    float h2 = (t0 >= 1) ? xp[(size_t)(t0 - 1) * (2 * DI)] : 0.f;

    float y = g_s[idx];
    #pragma unroll 4
    for (int t = t0; t < t0 + CL; t++) {
        float xt = xp[(size_t)t * (2 * DI)];
        float g  = gp[(size_t)t * (2 * DI)];
        float cv = fmaf(w0, h0, fmaf(w1, h1, fmaf(w2, h2, fmaf(w3, xt, bias))));
        h0 = h1; h1 = h2; h2 = xt;
        y = fmaf(alpha, y, cv);
        float sl = y * (1.f / (1.f + __expf(-y)));
        float v = sl * g;
        __half hh, ll;
        hsplit(v, hh, ll);
        g_acth[ao + (size_t)t * DI] = hh;
        g_actl[ao + (size_t)t * DI] = ll;
    }
}

// ---------------- launch (NO device-symbol references in host code) ----------------
extern "C" void kernel_launch(void* const* d_in, const int* in_sizes, int n_in,
                              void* d_out, int out_size) {
    const float* x          = (const float*)d_in[0];
    const float* norm_w     = (const float*)d_in[1];
    const float* norm_b     = (const float*)d_in[2];
    const float* in_proj_w  = (const float*)d_in[3];
    const float* conv_w     = (const float*)d_in[4];
    const float* conv_b     = (const float*)d_in[5];
    const float* out_proj_w = (const float*)d_in[6];
    const float* log_alpha  = (const float*)d_in[7];
    float* out = (float*)d_out;

    cudaFuncSetAttribute(gemm_h<1>, cudaFuncAttributeMaxDynamicSharedMemorySize, GEMM_SMEM);
    cudaFuncSetAttribute(gemm_h<2>, cudaFuncAttributeMaxDynamicSharedMemorySize, GEMM_SMEM);

    int n1 = 2 * DI * Dd / 4, n2 = Dd * DI / 4;
    wprep<1><<<(n1 + 255) / 256, 256>>>(in_proj_w);
    wprep<2><<<(n2 + 255) / 256, 256>>>(out_proj_w);

    ln_kernel<<<Mm, 256>>>(x, norm_w, norm_b);

    dim3 g1((2 * DI) / 128, Mm / 128);           // (32, 128)
    gemm_h<1><<<g1, 256, GEMM_SMEM>>>(nullptr, nullptr);

    scan_p1<<<(Bb * NC * DI) / 256, 256>>>(conv_w, conv_b, log_alpha);
    scan_p2<<<(Bb * DI) / 256, 256>>>(log_alpha);
    scan_p3<<<(Bb * NC * DI) / 256, 256>>>(conv_w, conv_b, log_alpha);

    dim3 g2(Dd / 128, Mm / 128);                 // (8, 128)
    gemm_h<2><<<g2, 256, GEMM_SMEM>>>(x, out);
}

// round 10
// speedup vs baseline: 7.3482x; 1.5269x over previous
#include <cuda_runtime.h>
#include <cuda_fp16.h>
#include <math.h>
#include <stdint.h>

#define Bb 4
#define Ss 4096
#define Dd 1024
#define DI 2048
#define HD 256
#define Mm (Bb * Ss)   // 16384 tokens
#define CL 64          // scan chunk length
#define NC (Ss / CL)   // 64 chunks

// ---------------- scratch (device-code references ONLY; never named in host code) ----
__device__ float g_xz[(size_t)Mm * 2 * DI];      // 256 MB (gemm1 out, fp32)
__device__ __half g_xnh[(size_t)Mm * Dd];        //  32 MB (LN out, fp16)
__device__ __half g_acth[(size_t)Mm * DI];       //  64 MB (scan out, fp16)
__device__ __half g_w1h[(size_t)2 * DI * Dd];    //   8 MB (in_proj fp16)
__device__ __half g_w2h[(size_t)Dd * DI];        //   4 MB (out_proj fp16)
__device__ float g_e[(size_t)Bb * NC * DI];      //   2 MB (chunk end values)
__device__ float g_s[(size_t)Bb * NC * DI];      //   2 MB (chunk init states)

// ================= helpers =================
__device__ __forceinline__ uint32_t smem_u32(const void* p) {
    uint32_t a;
    asm("{ .reg .u64 t; cvta.to.shared.u64 t, %1; cvt.u32.u64 %0, t; }" : "=r"(a) : "l"(p));
    return a;
}
__device__ __forceinline__ void cp16(uint32_t dst, const void* src) {
    asm volatile("cp.async.cg.shared.global [%0], [%1], 16;" :: "r"(dst), "l"(src));
}
__device__ __forceinline__ void cp_commit() { asm volatile("cp.async.commit_group;" ::: "memory"); }
template <int N> __device__ __forceinline__ void cp_wait() {
    asm volatile("cp.async.wait_group %0;" :: "n"(N) : "memory");
}
__device__ __forceinline__ void ldsm4(uint32_t& r0, uint32_t& r1, uint32_t& r2, uint32_t& r3,
                                      uint32_t addr) {
    asm volatile("ldmatrix.sync.aligned.m8n8.x4.shared.b16 {%0,%1,%2,%3}, [%4];"
                 : "=r"(r0), "=r"(r1), "=r"(r2), "=r"(r3) : "r"(addr));
}
// f16 m16n8k16: d(f32) += a(f16x2 x4) * b(f16x2 x2)
__device__ __forceinline__ void mma_f16(float* d, const uint32_t* a, const uint32_t* b) {
    asm volatile(
        "mma.sync.aligned.m16n8k16.row.col.f32.f16.f16.f32 "
        "{%0,%1,%2,%3}, {%4,%5,%6,%7}, {%8,%9}, {%0,%1,%2,%3};"
        : "+f"(d[0]), "+f"(d[1]), "+f"(d[2]), "+f"(d[3])
        : "r"(a[0]), "r"(a[1]), "r"(a[2]), "r"(a[3]), "r"(b[0]), "r"(b[1]));
}

// ---------------- weight round to fp16 ----------------
template <int WHICH>
__global__ void __launch_bounds__(256) wprep(const float* __restrict__ s) {
    __half* d = (WHICH == 1) ? g_w1h : g_w2h;
    const int n4 = (WHICH == 1) ? (2 * DI * Dd / 4) : (Dd * DI / 4);
    int i = blockIdx.x * 256 + threadIdx.x;
    if (i < n4) {
        float4 v = ((const float4*)s)[i];
        *(__half2*)(d + (size_t)i * 4)     = __halves2half2(__float2half_rn(v.x), __float2half_rn(v.y));
        *(__half2*)(d + (size_t)i * 4 + 2) = __halves2half2(__float2half_rn(v.z), __float2half_rn(v.w));
    }
}

// ---------------- LayerNorm (writes fp16) ----------------
__global__ void __launch_bounds__(256) ln_kernel(const float* __restrict__ x,
                                                 const float* __restrict__ w,
                                                 const float* __restrict__ bia) {
    int m = blockIdx.x;
    int t = threadIdx.x;
    const float4* xr = (const float4*)(x + (size_t)m * Dd);
    float4 xv = xr[t];
    float s  = xv.x + xv.y + xv.z + xv.w;
    float s2 = xv.x * xv.x + xv.y * xv.y + xv.z * xv.z + xv.w * xv.w;
    #pragma unroll
    for (int o = 16; o; o >>= 1) {
        s  += __shfl_xor_sync(0xffffffffu, s, o);
        s2 += __shfl_xor_sync(0xffffffffu, s2, o);
    }
    __shared__ float shs[8], shs2[8];
    int wid = t >> 5, lane = t & 31;
    if (lane == 0) { shs[wid] = s; shs2[wid] = s2; }
    __syncthreads();
    s = 0.f; s2 = 0.f;
    #pragma unroll
    for (int i = 0; i < 8; i++) { s += shs[i]; s2 += shs2[i]; }
    float mu  = s * (1.0f / Dd);
    float var = s2 * (1.0f / Dd) - mu * mu;
    float rstd = rsqrtf(var + 1e-5f);
    float4 wv = ((const float4*)w)[t];
    float4 bv = ((const float4*)bia)[t];
    float o0 = (xv.x - mu) * rstd * wv.x + bv.x;
    float o1 = (xv.y - mu) * rstd * wv.y + bv.y;
    float o2 = (xv.z - mu) * rstd * wv.z + bv.z;
    float o3 = (xv.w - mu) * rstd * wv.w + bv.w;
    size_t base = (size_t)m * Dd + 4 * t;
    *(__half2*)(g_xnh + base)     = __halves2half2(__float2half_rn(o0), __float2half_rn(o1));
    *(__half2*)(g_xnh + base + 2) = __halves2half2(__float2half_rn(o2), __float2half_rn(o3));
}

// ============ fp16 single-pass GEMM: C[m,n] = sum_k A[m,k]*W[n,k] (+res) ============
// Block 128x128, BK=32, 3-stage cp.async pipeline, 8 warps (4m x 2n), warp 32x64.
// smem: per stage 2 planes (A, W) of 128 rows x 40 halfs (pad 8) = 10240 B each.
// ldmatrix.x4 fragment loads; 80B row stride -> conflict-free, 16B-aligned.
#define HST 40
#define PLANE_B (128 * HST * 2)            // 10240
#define STAGE_B (2 * PLANE_B)              // 20480
#define GEMM_SMEM (3 * STAGE_B)            // 61440

template <int WHICH>                        // 1: xn @ w1 -> g_xz ; 2: act @ w2 + R -> Cout
__global__ void __launch_bounds__(256, 2) gemm_h(const float* __restrict__ R,
                                                 float* __restrict__ Cout) {
    constexpr int NTOT = (WHICH == 1) ? 2 * DI : Dd;
    constexpr int KK   = (WHICH == 1) ? Dd : DI;
    constexpr bool RESADD = (WHICH == 2);
    const __half* Ap = (WHICH == 1) ? g_xnh : g_acth;
    const __half* Wp = (WHICH == 1) ? g_w1h : g_w2h;
    float* C = (WHICH == 1) ? g_xz : Cout;

    extern __shared__ char smraw[];
    uint32_t sb = smem_u32(smraw);
    int tid = threadIdx.x, lane = tid & 31, wid = tid >> 5;
    int wm = wid & 3, wn = wid >> 2;
    int bm = blockIdx.y * 128, bn = blockIdx.x * 128;
    int lr = lane >> 2, lc = lane & 3;

    // producer coords: row r (0..127), 16B chunk pair
    int r = tid >> 1, cp8 = (tid & 1) * 16;    // halfs offset
    const __half* pA = Ap + (size_t)(bm + r) * KK + cp8;
    const __half* pW = Wp + (size_t)(bn + r) * KK + cp8;
    uint32_t dA = sb + (uint32_t)(r * HST + cp8) * 2;
    uint32_t dW = dA + PLANE_B;

    const int NIT = KK / 32;
    #define ISSUE(s, k0) do {                             \
        cp16(dA + (s) * STAGE_B,      pA + (k0));         \
        cp16(dA + (s) * STAGE_B + 16, pA + (k0) + 8);     \
        cp16(dW + (s) * STAGE_B,      pW + (k0));         \
        cp16(dW + (s) * STAGE_B + 16, pW + (k0) + 8);     \
        cp_commit();                                      \
    } while (0)

    ISSUE(0, 0);
    ISSUE(1, 32);

    float acc[2][8][4];
    #pragma unroll
    for (int mt = 0; mt < 2; mt++)
        #pragma unroll
        for (int nt = 0; nt < 8; nt++)
            #pragma unroll
            for (int q = 0; q < 4; q++) acc[mt][nt][q] = 0.f;

    // per-lane LDSM address components (in halfs)
    int arow = lane & 15;
    int akoff = (lane >> 4) * 8;
    int brow = (lane & 7) + ((lane & 16) ? 8 : 0);
    int bkoff = (lane & 8) ? 8 : 0;

    for (int i = 0; i < NIT; i++) {
        int s = i % 3;
        if (i + 1 < NIT) cp_wait<1>(); else cp_wait<0>();
        __syncthreads();
        if (i + 2 < NIT) ISSUE((i + 2) % 3, (i + 2) * 32);

        uint32_t As = sb + s * STAGE_B;
        uint32_t Ws = As + PLANE_B;

        #pragma unroll
        for (int ks = 0; ks < 2; ks++) {
            int k0 = ks * 16;
            uint32_t a[2][4];
            #pragma unroll
            for (int mt = 0; mt < 2; mt++) {
                uint32_t off = (uint32_t)((wm * 32 + mt * 16 + arow) * HST + k0 + akoff) * 2;
                ldsm4(a[mt][0], a[mt][1], a[mt][2], a[mt][3], As + off);
            }
            #pragma unroll
            for (int ntp = 0; ntp < 4; ntp++) {
                uint32_t b0, b1, b2, b3;
                uint32_t off = (uint32_t)((wn * 64 + ntp * 16 + brow) * HST + k0 + bkoff) * 2;
                ldsm4(b0, b1, b2, b3, Ws + off);
                uint32_t bA[2] = { b0, b1 };
                uint32_t bB[2] = { b2, b3 };
                #pragma unroll
                for (int mt = 0; mt < 2; mt++) {
                    mma_f16(acc[mt][2 * ntp],     a[mt], bA);
                    mma_f16(acc[mt][2 * ntp + 1], a[mt], bB);
                }
            }
        }
    }
    #undef ISSUE

    // epilogue
    #pragma unroll
    for (int mt = 0; mt < 2; mt++) {
        int m0 = bm + wm * 32 + mt * 16 + lr;
        #pragma unroll
        for (int nt = 0; nt < 8; nt++) {
            int n = bn + wn * 64 + nt * 8 + lc * 2;
            float* C0 = C + (size_t)m0 * NTOT + n;
            float* C1 = C + (size_t)(m0 + 8) * NTOT + n;
            float2 v0 = make_float2(acc[mt][nt][0], acc[mt][nt][1]);
            float2 v1 = make_float2(acc[mt][nt][2], acc[mt][nt][3]);
            if (RESADD) {
                const float2 r0 = *(const float2*)(R + (size_t)m0 * NTOT + n);
                const float2 r1 = *(const float2*)(R + (size_t)(m0 + 8) * NTOT + n);
                v0.x += r0.x; v0.y += r0.y;
                v1.x += r1.x; v1.y += r1.y;
            }
            *(float2*)C0 = v0;
            *(float2*)C1 = v1;
        }
    }
}

// ======== chunked parallel scan: y_t = alpha*y_{t-1} + conv(x)_t ========
__global__ void __launch_bounds__(256) scan_p1(const float* __restrict__ conv_w,
                                               const float* __restrict__ conv_b,
                                               const float* __restrict__ log_alpha) {
    int idx = blockIdx.x * 256 + threadIdx.x;
    int c = idx & (DI - 1);
    int j = (idx >> 11) & (NC - 1);
    int b = idx >> 17;
    float w0 = conv_w[c * 4 + 0], w1 = conv_w[c * 4 + 1];
    float w2 = conv_w[c * 4 + 2], w3 = conv_w[c * 4 + 3];
    float bias = conv_b[c];
    float alpha = 1.f / (1.f + __expf(-log_alpha[c / HD]));

    const float* xp = g_xz + (size_t)b * Ss * (2 * DI) + c;
    int t0 = j * CL;
    float h0 = (t0 >= 3) ? xp[(size_t)(t0 - 3) * (2 * DI)] : 0.f;
    float h1 = (t0 >= 2) ? xp[(size_t)(t0 - 2) * (2 * DI)] : 0.f;
    float h2 = (t0 >= 1) ? xp[(size_t)(t0 - 1) * (2 * DI)] : 0.f;

    float e = 0.f;
    #pragma unroll 4
    for (int t = t0; t < t0 + CL; t++) {
        float xt = xp[(size_t)t * (2 * DI)];
        float cv = fmaf(w0, h0, fmaf(w1, h1, fmaf(w2, h2, fmaf(w3, xt, bias))));
        h0 = h1; h1 = h2; h2 = xt;
        e = fmaf(alpha, e, cv);
    }
    g_e[idx] = e;
}

__global__ void __launch_bounds__(256) scan_p2(const float* __restrict__ log_alpha) {
    int idx = blockIdx.x * 256 + threadIdx.x;
    int c = idx & (DI - 1);
    int b = idx >> 11;
    float alpha = 1.f / (1.f + __expf(-log_alpha[c / HD]));
    float aL = powf(alpha, (float)CL);
    float s = 0.f;
    size_t base = (size_t)b * NC * DI + c;
    #pragma unroll 8
    for (int j = 0; j < NC; j++) {
        g_s[base + (size_t)j * DI] = s;
        s = fmaf(aL, s, g_e[base + (size_t)j * DI]);
    }
}

__global__ void __launch_bounds__(256) scan_p3(const float* __restrict__ conv_w,
                                               const float* __restrict__ conv_b,
                                               const float* __restrict__ log_alpha) {
    int idx = blockIdx.x * 256 + threadIdx.x;
    int c = idx & (DI - 1);
    int j = (idx >> 11) & (NC - 1);
    int b = idx >> 17;
    float w0 = conv_w[c * 4 + 0], w1 = conv_w[c * 4 + 1];
    float w2 = conv_w[c * 4 + 2], w3 = conv_w[c * 4 + 3];
    float bias = conv_b[c];
    float alpha = 1.f / (1.f + __expf(-log_alpha[c / HD]));

    const float* xp = g_xz + (size_t)b * Ss * (2 * DI) + c;
    const float* gp = xp + DI;
    size_t ao = (size_t)b * Ss * DI + c;
    int t0 = j * CL;
    float h0 = (t0 >= 3) ? xp[(size_t)(t0 - 3) * (2 * DI)] : 0.f;
    float h1 = (t0 >= 2) ? xp[(size_t)(t0 - 2) * (2 * DI)] : 0.f;
    float h2 = (t0 >= 1) ? xp[(size_t)(t0 - 1) * (2 * DI)] : 0.f;

    float y = g_s[idx];
    #pragma unroll 4
    for (int t = t0; t < t0 + CL; t++) {
        float xt = xp[(size_t)t * (2 * DI)];
        float g  = gp[(size_t)t * (2 * DI)];
        float cv = fmaf(w0, h0, fmaf(w1, h1, fmaf(w2, h2, fmaf(w3, xt, bias))));
        h0 = h1; h1 = h2; h2 = xt;
        y = fmaf(alpha, y, cv);
        float sl = y * (1.f / (1.f + __expf(-y)));
        g_acth[ao + (size_t)t * DI] = __float2half_rn(sl * g);
    }
}

// ---------------- launch (NO device-symbol references in host code) ----------------
extern "C" void kernel_launch(void* const* d_in, const int* in_sizes, int n_in,
                              void* d_out, int out_size) {
    const float* x          = (const float*)d_in[0];
    const float* norm_w     = (const float*)d_in[1];
    const float* norm_b     = (const float*)d_in[2];
    const float* in_proj_w  = (const float*)d_in[3];
    const float* conv_w     = (const float*)d_in[4];
    const float* conv_b     = (const float*)d_in[5];
    const float* out_proj_w = (const float*)d_in[6];
    const float* log_alpha  = (const float*)d_in[7];
    float* out = (float*)d_out;

    cudaFuncSetAttribute(gemm_h<1>, cudaFuncAttributeMaxDynamicSharedMemorySize, GEMM_SMEM);
    cudaFuncSetAttribute(gemm_h<2>, cudaFuncAttributeMaxDynamicSharedMemorySize, GEMM_SMEM);

    int n1 = 2 * DI * Dd / 4, n2 = Dd * DI / 4;
    wprep<1><<<(n1 + 255) / 256, 256>>>(in_proj_w);
    wprep<2><<<(n2 + 255) / 256, 256>>>(out_proj_w);

    ln_kernel<<<Mm, 256>>>(x, norm_w, norm_b);

    dim3 g1((2 * DI) / 128, Mm / 128);           // (32, 128)
    gemm_h<1><<<g1, 256, GEMM_SMEM>>>(nullptr, nullptr);

    scan_p1<<<(Bb * NC * DI) / 256, 256>>>(conv_w, conv_b, log_alpha);
    scan_p2<<<(Bb * DI) / 256, 256>>>(log_alpha);
    scan_p3<<<(Bb * NC * DI) / 256, 256>>>(conv_w, conv_b, log_alpha);

    dim3 g2(Dd / 128, Mm / 128);                 // (8, 128)
    gemm_h<2><<<g2, 256, GEMM_SMEM>>>(x, out);
}

// round 11
// speedup vs baseline: 8.4128x; 1.1449x over previous
#include <cuda_runtime.h>
#include <cuda_fp16.h>
#include <math.h>
#include <stdint.h>

#define Bb 4
#define Ss 4096
#define Dd 1024
#define DI 2048
#define HD 256
#define Mm (Bb * Ss)   // 16384 tokens
#define CL 64          // scan chunk length
#define NC (Ss / CL)   // 64 chunks

// ---------------- scratch (device-code references ONLY; never named in host code) ----
__device__ __half g_xz[(size_t)Mm * 2 * DI];     // 128 MB (gemm1 out, fp16)
__device__ __half g_xnh[(size_t)Mm * Dd];        //  32 MB (LN out, fp16)
__device__ __half g_acth[(size_t)Mm * DI];       //  64 MB (scan out, fp16)
__device__ __half g_w1h[(size_t)2 * DI * Dd];    //   8 MB (in_proj fp16)
__device__ __half g_w2h[(size_t)Dd * DI];        //   4 MB (out_proj fp16)
__device__ float g_e[(size_t)Bb * NC * DI];      //   2 MB (chunk end values)
__device__ float g_s[(size_t)Bb * NC * DI];      //   2 MB (chunk init states)

// ================= helpers =================
__device__ __forceinline__ uint32_t smem_u32(const void* p) {
    uint32_t a;
    asm("{ .reg .u64 t; cvta.to.shared.u64 t, %1; cvt.u32.u64 %0, t; }" : "=r"(a) : "l"(p));
    return a;
}
__device__ __forceinline__ void cp16(uint32_t dst, const void* src) {
    asm volatile("cp.async.cg.shared.global [%0], [%1], 16;" :: "r"(dst), "l"(src));
}
__device__ __forceinline__ void cp_commit() { asm volatile("cp.async.commit_group;" ::: "memory"); }
template <int N> __device__ __forceinline__ void cp_wait() {
    asm volatile("cp.async.wait_group %0;" :: "n"(N) : "memory");
}
__device__ __forceinline__ void ldsm4(uint32_t& r0, uint32_t& r1, uint32_t& r2, uint32_t& r3,
                                      uint32_t addr) {
    asm volatile("ldmatrix.sync.aligned.m8n8.x4.shared.b16 {%0,%1,%2,%3}, [%4];"
                 : "=r"(r0), "=r"(r1), "=r"(r2), "=r"(r3) : "r"(addr));
}
__device__ __forceinline__ void mma_f16(float* d, const uint32_t* a, const uint32_t* b) {
    asm volatile(
        "mma.sync.aligned.m16n8k16.row.col.f32.f16.f16.f32 "
        "{%0,%1,%2,%3}, {%4,%5,%6,%7}, {%8,%9}, {%0,%1,%2,%3};"
        : "+f"(d[0]), "+f"(d[1]), "+f"(d[2]), "+f"(d[3])
        : "r"(a[0]), "r"(a[1]), "r"(a[2]), "r"(a[3]), "r"(b[0]), "r"(b[1]));
}

// ---------------- weight round to fp16 ----------------
template <int WHICH>
__global__ void __launch_bounds__(256) wprep(const float* __restrict__ s) {
    __half* d = (WHICH == 1) ? g_w1h : g_w2h;
    const int n4 = (WHICH == 1) ? (2 * DI * Dd / 4) : (Dd * DI / 4);
    int i = blockIdx.x * 256 + threadIdx.x;
    if (i < n4) {
        float4 v = ((const float4*)s)[i];
        *(__half2*)(d + (size_t)i * 4)     = __halves2half2(__float2half_rn(v.x), __float2half_rn(v.y));
        *(__half2*)(d + (size_t)i * 4 + 2) = __halves2half2(__float2half_rn(v.z), __float2half_rn(v.w));
    }
}

// ---------------- LayerNorm (writes fp16) ----------------
__global__ void __launch_bounds__(256) ln_kernel(const float* __restrict__ x,
                                                 const float* __restrict__ w,
                                                 const float* __restrict__ bia) {
    int m = blockIdx.x;
    int t = threadIdx.x;
    const float4* xr = (const float4*)(x + (size_t)m * Dd);
    float4 xv = xr[t];
    float s  = xv.x + xv.y + xv.z + xv.w;
    float s2 = xv.x * xv.x + xv.y * xv.y + xv.z * xv.z + xv.w * xv.w;
    #pragma unroll
    for (int o = 16; o; o >>= 1) {
        s  += __shfl_xor_sync(0xffffffffu, s, o);
        s2 += __shfl_xor_sync(0xffffffffu, s2, o);
    }
    __shared__ float shs[8], shs2[8];
    int wid = t >> 5, lane = t & 31;
    if (lane == 0) { shs[wid] = s; shs2[wid] = s2; }
    __syncthreads();
    s = 0.f; s2 = 0.f;
    #pragma unroll
    for (int i = 0; i < 8; i++) { s += shs[i]; s2 += shs2[i]; }
    float mu  = s * (1.0f / Dd);
    float var = s2 * (1.0f / Dd) - mu * mu;
    float rstd = rsqrtf(var + 1e-5f);
    float4 wv = ((const float4*)w)[t];
    float4 bv = ((const float4*)bia)[t];
    float o0 = (xv.x - mu) * rstd * wv.x + bv.x;
    float o1 = (xv.y - mu) * rstd * wv.y + bv.y;
    float o2 = (xv.z - mu) * rstd * wv.z + bv.z;
    float o3 = (xv.w - mu) * rstd * wv.w + bv.w;
    size_t base = (size_t)m * Dd + 4 * t;
    *(__half2*)(g_xnh + base)     = __halves2half2(__float2half_rn(o0), __float2half_rn(o1));
    *(__half2*)(g_xnh + base + 2) = __halves2half2(__float2half_rn(o2), __float2half_rn(o3));
}

// ============ fp16 GEMM: CTA tile 256x128, warp tile 64x64, BK=64, 3-stage ============
// 8 warps (4 wm x 2 wn), 1 CTA/SM (reg-limited), smem 166KB.
// row stride 72 halfs = 144B: 16B-aligned, conflict-free LDSM (4r mod 32 distinct).
#define HST2 72
#define A_PL (256 * HST2 * 2)              // 36864
#define B_PL (128 * HST2 * 2)              // 18432
#define STG  (A_PL + B_PL)                 // 55296
#define GEMM_SMEM (3 * STG)                // 165888

template <int WHICH>                        // 1: xn @ w1 -> g_xz(half) ; 2: act @ w2 + R -> out(f32)
__global__ void __launch_bounds__(256) gemm_h(const float* __restrict__ R,
                                              float* __restrict__ Cout) {
    constexpr int NTOT = (WHICH == 1) ? 2 * DI : Dd;
    constexpr int KK   = (WHICH == 1) ? Dd : DI;
    const __half* Ap = (WHICH == 1) ? g_xnh : g_acth;
    const __half* Wp = (WHICH == 1) ? g_w1h : g_w2h;

    extern __shared__ char smraw[];
    uint32_t sb = smem_u32(smraw);
    int tid = threadIdx.x, lane = tid & 31, wid = tid >> 5;
    int wm = wid & 3, wn = wid >> 2;               // 4 x 2
    int bm = blockIdx.y * 256, bn = blockIdx.x * 128;
    int lr = lane >> 2, lc = lane & 3;

    // producer coords: 8 threads per row-chunk group
    int pr = tid >> 3, pc = (tid & 7) * 8;          // pc in halfs (16B chunks)
    const __half* pA = Ap + (size_t)(bm + pr) * KK + pc;
    const __half* pW = Wp + (size_t)(bn + pr) * KK + pc;
    uint32_t dA = sb + (uint32_t)(pr * HST2 + pc) * 2;
    uint32_t dW = sb + A_PL + (uint32_t)(pr * HST2 + pc) * 2;

    const int NIT = KK / 64;
    #define ISSUE(s, k0) do {                                                   \
        _Pragma("unroll")                                                       \
        for (int j = 0; j < 8; j++)                                             \
            cp16(dA + (s) * STG + j * 32 * HST2 * 2, pA + (size_t)j * 32 * KK + (k0)); \
        _Pragma("unroll")                                                       \
        for (int j = 0; j < 4; j++)                                             \
            cp16(dW + (s) * STG + j * 32 * HST2 * 2, pW + (size_t)j * 32 * KK + (k0)); \
        cp_commit();                                                            \
    } while (0)

    ISSUE(0, 0);
    ISSUE(1, 64);

    float acc[4][8][4];
    #pragma unroll
    for (int mt = 0; mt < 4; mt++)
        #pragma unroll
        for (int nt = 0; nt < 8; nt++)
            #pragma unroll
            for (int q = 0; q < 4; q++) acc[mt][nt][q] = 0.f;

    // per-lane LDSM address components (in halfs)
    int arow = lane & 15;
    int akoff = (lane >> 4) * 8;
    int brow = (lane & 7) + ((lane & 16) ? 8 : 0);
    int bkoff = (lane & 8) ? 8 : 0;

    for (int i = 0; i < NIT; i++) {
        int s = i % 3;
        if (i + 1 < NIT) cp_wait<1>(); else cp_wait<0>();
        __syncthreads();
        if (i + 2 < NIT) ISSUE((i + 2) % 3, (i + 2) * 64);

        uint32_t As = sb + s * STG;
        uint32_t Ws = As + A_PL;

        #pragma unroll
        for (int ks = 0; ks < 4; ks++) {
            int k0 = ks * 16;
            uint32_t a[4][4];
            #pragma unroll
            for (int mt = 0; mt < 4; mt++) {
                uint32_t off = (uint32_t)((wm * 64 + mt * 16 + arow) * HST2 + k0 + akoff) * 2;
                ldsm4(a[mt][0], a[mt][1], a[mt][2], a[mt][3], As + off);
            }
            #pragma unroll
            for (int ntp = 0; ntp < 4; ntp++) {
                uint32_t b0, b1, b2, b3;
                uint32_t off = (uint32_t)((wn * 64 + ntp * 16 + brow) * HST2 + k0 + bkoff) * 2;
                ldsm4(b0, b1, b2, b3, Ws + off);
                uint32_t bA[2] = { b0, b1 };
                uint32_t bB[2] = { b2, b3 };
                #pragma unroll
                for (int mt = 0; mt < 4; mt++) {
                    mma_f16(acc[mt][2 * ntp],     a[mt], bA);
                    mma_f16(acc[mt][2 * ntp + 1], a[mt], bB);
                }
            }
        }
    }
    #undef ISSUE

    // epilogue
    #pragma unroll
    for (int mt = 0; mt < 4; mt++) {
        int m0 = bm + wm * 64 + mt * 16 + lr;
        #pragma unroll
        for (int nt = 0; nt < 8; nt++) {
            int n = bn + wn * 64 + nt * 8 + lc * 2;
            if (WHICH == 1) {
                __half* C0 = g_xz + (size_t)m0 * NTOT + n;
                __half* C1 = g_xz + (size_t)(m0 + 8) * NTOT + n;
                *(__half2*)C0 = __halves2half2(__float2half_rn(acc[mt][nt][0]),
                                               __float2half_rn(acc[mt][nt][1]));
                *(__half2*)C1 = __halves2half2(__float2half_rn(acc[mt][nt][2]),
                                               __float2half_rn(acc[mt][nt][3]));
            } else {
                float* C0 = Cout + (size_t)m0 * NTOT + n;
                float* C1 = Cout + (size_t)(m0 + 8) * NTOT + n;
                const float2 r0 = *(const float2*)(R + (size_t)m0 * NTOT + n);
                const float2 r1 = *(const float2*)(R + (size_t)(m0 + 8) * NTOT + n);
                *(float2*)C0 = make_float2(acc[mt][nt][0] + r0.x, acc[mt][nt][1] + r0.y);
                *(float2*)C1 = make_float2(acc[mt][nt][2] + r1.x, acc[mt][nt][3] + r1.y);
            }
        }
    }
}

// ======== chunked parallel scan: y_t = alpha*y_{t-1} + conv(x)_t (reads fp16 xz) ====
__global__ void __launch_bounds__(256) scan_p1(const float* __restrict__ conv_w,
                                               const float* __restrict__ conv_b,
                                               const float* __restrict__ log_alpha) {
    int idx = blockIdx.x * 256 + threadIdx.x;
    int c = idx & (DI - 1);
    int j = (idx >> 11) & (NC - 1);
    int b = idx >> 17;
    float w0 = conv_w[c * 4 + 0], w1 = conv_w[c * 4 + 1];
    float w2 = conv_w[c * 4 + 2], w3 = conv_w[c * 4 + 3];
    float bias = conv_b[c];
    float alpha = 1.f / (1.f + __expf(-log_alpha[c / HD]));

    const __half* xp = g_xz + (size_t)b * Ss * (2 * DI) + c;
    int t0 = j * CL;
    float h0 = (t0 >= 3) ? __half2float(xp[(size_t)(t0 - 3) * (2 * DI)]) : 0.f;
    float h1 = (t0 >= 2) ? __half2float(xp[(size_t)(t0 - 2) * (2 * DI)]) : 0.f;
    float h2 = (t0 >= 1) ? __half2float(xp[(size_t)(t0 - 1) * (2 * DI)]) : 0.f;

    float e = 0.f;
    #pragma unroll 4
    for (int t = t0; t < t0 + CL; t++) {
        float xt = __half2float(xp[(size_t)t * (2 * DI)]);
        float cv = fmaf(w0, h0, fmaf(w1, h1, fmaf(w2, h2, fmaf(w3, xt, bias))));
        h0 = h1; h1 = h2; h2 = xt;
        e = fmaf(alpha, e, cv);
    }
    g_e[idx] = e;
}

__global__ void __launch_bounds__(256) scan_p2(const float* __restrict__ log_alpha) {
    int idx = blockIdx.x * 256 + threadIdx.x;
    int c = idx & (DI - 1);
    int b = idx >> 11;
    float alpha = 1.f / (1.f + __expf(-log_alpha[c / HD]));
    float aL = powf(alpha, (float)CL);
    float s = 0.f;
    size_t base = (size_t)b * NC * DI + c;
    #pragma unroll 8
    for (int j = 0; j < NC; j++) {
        g_s[base + (size_t)j * DI] = s;
        s = fmaf(aL, s, g_e[base + (size_t)j * DI]);
    }
}

__global__ void __launch_bounds__(256) scan_p3(const float* __restrict__ conv_w,
                                               const float* __restrict__ conv_b,
                                               const float* __restrict__ log_alpha) {
    int idx = blockIdx.x * 256 + threadIdx.x;
    int c = idx & (DI - 1);
    int j = (idx >> 11) & (NC - 1);
    int b = idx >> 17;
    float w0 = conv_w[c * 4 + 0], w1 = conv_w[c * 4 + 1];
    float w2 = conv_w[c * 4 + 2], w3 = conv_w[c * 4 + 3];
    float bias = conv_b[c];
    float alpha = 1.f / (1.f + __expf(-log_alpha[c / HD]));

    const __half* xp = g_xz + (size_t)b * Ss * (2 * DI) + c;
    const __half* gp = xp + DI;
    size_t ao = (size_t)b * Ss * DI + c;
    int t0 = j * CL;
    float h0 = (t0 >= 3) ? __half2float(xp[(size_t)(t0 - 3) * (2 * DI)]) : 0.f;
    float h1 = (t0 >= 2) ? __half2float(xp[(size_t)(t0 - 2) * (2 * DI)]) : 0.f;
    float h2 = (t0 >= 1) ? __half2float(xp[(size_t)(t0 - 1) * (2 * DI)]) : 0.f;

    float y = g_s[idx];
    #pragma unroll 4
    for (int t = t0; t < t0 + CL; t++) {
        float xt = __half2float(xp[(size_t)t * (2 * DI)]);
        float g  = __half2float(gp[(size_t)t * (2 * DI)]);
        float cv = fmaf(w0, h0, fmaf(w1, h1, fmaf(w2, h2, fmaf(w3, xt, bias))));
        h0 = h1; h1 = h2; h2 = xt;
        y = fmaf(alpha, y, cv);
        float sl = y * (1.f / (1.f + __expf(-y)));
        g_acth[ao + (size_t)t * DI] = __float2half_rn(sl * g);
    }
}

// ---------------- launch (NO device-symbol references in host code) ----------------
extern "C" void kernel_launch(void* const* d_in, const int* in_sizes, int n_in,
                              void* d_out, int out_size) {
    const float* x          = (const float*)d_in[0];
    const float* norm_w     = (const float*)d_in[1];
    const float* norm_b     = (const float*)d_in[2];
    const float* in_proj_w  = (const float*)d_in[3];
    const float* conv_w     = (const float*)d_in[4];
    const float* conv_b     = (const float*)d_in[5];
    const float* out_proj_w = (const float*)d_in[6];
    const float* log_alpha  = (const float*)d_in[7];
    float* out = (float*)d_out;

    cudaFuncSetAttribute(gemm_h<1>, cudaFuncAttributeMaxDynamicSharedMemorySize, GEMM_SMEM);
    cudaFuncSetAttribute(gemm_h<2>, cudaFuncAttributeMaxDynamicSharedMemorySize, GEMM_SMEM);

    int n1 = 2 * DI * Dd / 4, n2 = Dd * DI / 4;
    wprep<1><<<(n1 + 255) / 256, 256>>>(in_proj_w);
    wprep<2><<<(n2 + 255) / 256, 256>>>(out_proj_w);

    ln_kernel<<<Mm, 256>>>(x, norm_w, norm_b);

    dim3 g1((2 * DI) / 128, Mm / 256);           // (32, 64)
    gemm_h<1><<<g1, 256, GEMM_SMEM>>>(nullptr, nullptr);

    scan_p1<<<(Bb * NC * DI) / 256, 256>>>(conv_w, conv_b, log_alpha);
    scan_p2<<<(Bb * DI) / 256, 256>>>(log_alpha);
    scan_p3<<<(Bb * NC * DI) / 256, 256>>>(conv_w, conv_b, log_alpha);

    dim3 g2(Dd / 128, Mm / 256);                 // (8, 64)
    gemm_h<2><<<g2, 256, GEMM_SMEM>>>(x, out);
}

// round 12
// speedup vs baseline: 8.4258x; 1.0015x over previous
#include <cuda_runtime.h>
#include <cuda_fp16.h>
#include <math.h>
#include <stdint.h>

#define Bb 4
#define Ss 4096
#define Dd 1024
#define DI 2048
#define HD 256
#define Mm (Bb * Ss)   // 16384 tokens
#define CL 64          // scan chunk length
#define NC (Ss / CL)   // 64 chunks

// ---------------- scratch (device-code references ONLY; never named in host code) ----
__device__ __half g_xz[(size_t)Mm * 2 * DI];     // 128 MB (gemm1 out, fp16)
__device__ __half g_xnh[(size_t)Mm * Dd];        //  32 MB (LN out, fp16)
__device__ __half g_acth[(size_t)Mm * DI];       //  64 MB (scan out, fp16)
__device__ __half g_w1h[(size_t)2 * DI * Dd];    //   8 MB (in_proj fp16)
__device__ __half g_w2h[(size_t)Dd * DI];        //   4 MB (out_proj fp16)
__device__ float g_e[(size_t)Bb * NC * DI];      //   2 MB (chunk end values)
__device__ float g_s[(size_t)Bb * NC * DI];      //   2 MB (chunk init states)

// ================= helpers =================
__device__ __forceinline__ uint32_t smem_u32(const void* p) {
    uint32_t a;
    asm("{ .reg .u64 t; cvta.to.shared.u64 t, %1; cvt.u32.u64 %0, t; }" : "=r"(a) : "l"(p));
    return a;
}
__device__ __forceinline__ void cp16(uint32_t dst, const void* src) {
    asm volatile("cp.async.cg.shared.global [%0], [%1], 16;" :: "r"(dst), "l"(src));
}
__device__ __forceinline__ void cp_commit() { asm volatile("cp.async.commit_group;" ::: "memory"); }
template <int N> __device__ __forceinline__ void cp_wait() {
    asm volatile("cp.async.wait_group %0;" :: "n"(N) : "memory");
}
__device__ __forceinline__ void ldsm4(uint32_t& r0, uint32_t& r1, uint32_t& r2, uint32_t& r3,
                                      uint32_t addr) {
    asm volatile("ldmatrix.sync.aligned.m8n8.x4.shared.b16 {%0,%1,%2,%3}, [%4];"
                 : "=r"(r0), "=r"(r1), "=r"(r2), "=r"(r3) : "r"(addr));
}
__device__ __forceinline__ void mma_f16(float* d, const uint32_t* a, const uint32_t* b) {
    asm volatile(
        "mma.sync.aligned.m16n8k16.row.col.f32.f16.f16.f32 "
        "{%0,%1,%2,%3}, {%4,%5,%6,%7}, {%8,%9}, {%0,%1,%2,%3};"
        : "+f"(d[0]), "+f"(d[1]), "+f"(d[2]), "+f"(d[3])
        : "r"(a[0]), "r"(a[1]), "r"(a[2]), "r"(a[3]), "r"(b[0]), "r"(b[1]));
}

// ---------------- weight round to fp16 ----------------
template <int WHICH>
__global__ void __launch_bounds__(256) wprep(const float* __restrict__ s) {
    __half* d = (WHICH == 1) ? g_w1h : g_w2h;
    const int n4 = (WHICH == 1) ? (2 * DI * Dd / 4) : (Dd * DI / 4);
    int i = blockIdx.x * 256 + threadIdx.x;
    if (i < n4) {
        float4 v = ((const float4*)s)[i];
        *(__half2*)(d + (size_t)i * 4)     = __halves2half2(__float2half_rn(v.x), __float2half_rn(v.y));
        *(__half2*)(d + (size_t)i * 4 + 2) = __halves2half2(__float2half_rn(v.z), __float2half_rn(v.w));
    }
}

// ---------------- LayerNorm (writes fp16) ----------------
__global__ void __launch_bounds__(256) ln_kernel(const float* __restrict__ x,
                                                 const float* __restrict__ w,
                                                 const float* __restrict__ bia) {
    int m = blockIdx.x;
    int t = threadIdx.x;
    const float4* xr = (const float4*)(x + (size_t)m * Dd);
    float4 xv = xr[t];
    float s  = xv.x + xv.y + xv.z + xv.w;
    float s2 = xv.x * xv.x + xv.y * xv.y + xv.z * xv.z + xv.w * xv.w;
    #pragma unroll
    for (int o = 16; o; o >>= 1) {
        s  += __shfl_xor_sync(0xffffffffu, s, o);
        s2 += __shfl_xor_sync(0xffffffffu, s2, o);
    }
    __shared__ float shs[8], shs2[8];
    int wid = t >> 5, lane = t & 31;
    if (lane == 0) { shs[wid] = s; shs2[wid] = s2; }
    __syncthreads();
    s = 0.f; s2 = 0.f;
    #pragma unroll
    for (int i = 0; i < 8; i++) { s += shs[i]; s2 += shs2[i]; }
    float mu  = s * (1.0f / Dd);
    float var = s2 * (1.0f / Dd) - mu * mu;
    float rstd = rsqrtf(var + 1e-5f);
    float4 wv = ((const float4*)w)[t];
    float4 bv = ((const float4*)bia)[t];
    float o0 = (xv.x - mu) * rstd * wv.x + bv.x;
    float o1 = (xv.y - mu) * rstd * wv.y + bv.y;
    float o2 = (xv.z - mu) * rstd * wv.z + bv.z;
    float o3 = (xv.w - mu) * rstd * wv.w + bv.w;
    size_t base = (size_t)m * Dd + 4 * t;
    *(__half2*)(g_xnh + base)     = __halves2half2(__float2half_rn(o0), __float2half_rn(o1));
    *(__half2*)(g_xnh + base + 2) = __halves2half2(__float2half_rn(o2), __float2half_rn(o3));
}

// ============ fp16 GEMM: CTA 256x128, warp 64x64, BK=64, 3-stage, frag double-buffer ====
#define HST2 72
#define A_PL (256 * HST2 * 2)              // 36864
#define B_PL (128 * HST2 * 2)              // 18432
#define STG  (A_PL + B_PL)                 // 55296
#define GEMM_SMEM (3 * STG)                // 165888

template <int WHICH>                        // 1: xn @ w1 -> g_xz(half) ; 2: act @ w2 + R -> out(f32)
__global__ void __launch_bounds__(256) gemm_h(const float* __restrict__ R,
                                              float* __restrict__ Cout) {
    constexpr int NTOT = (WHICH == 1) ? 2 * DI : Dd;
    constexpr int KK   = (WHICH == 1) ? Dd : DI;
    const __half* Ap = (WHICH == 1) ? g_xnh : g_acth;
    const __half* Wp = (WHICH == 1) ? g_w1h : g_w2h;

    extern __shared__ char smraw[];
    uint32_t sb = smem_u32(smraw);
    int tid = threadIdx.x, lane = tid & 31, wid = tid >> 5;
    int wm = wid & 3, wn = wid >> 2;               // 4 x 2
    int bm = blockIdx.y * 256, bn = blockIdx.x * 128;
    int lr = lane >> 2, lc = lane & 3;

    // producer coords
    int pr = tid >> 3, pc = (tid & 7) * 8;
    const __half* pA = Ap + (size_t)(bm + pr) * KK + pc;
    const __half* pW = Wp + (size_t)(bn + pr) * KK + pc;
    uint32_t dA = sb + (uint32_t)(pr * HST2 + pc) * 2;
    uint32_t dW = sb + A_PL + (uint32_t)(pr * HST2 + pc) * 2;

    const int NIT = KK / 64;
    #define ISSUE(s, k0) do {                                                   \
        _Pragma("unroll")                                                       \
        for (int j = 0; j < 8; j++)                                             \
            cp16(dA + (s) * STG + j * 32 * HST2 * 2, pA + (size_t)j * 32 * KK + (k0)); \
        _Pragma("unroll")                                                       \
        for (int j = 0; j < 4; j++)                                             \
            cp16(dW + (s) * STG + j * 32 * HST2 * 2, pW + (size_t)j * 32 * KK + (k0)); \
        cp_commit();                                                            \
    } while (0)

    ISSUE(0, 0);
    ISSUE(1, 64);

    float acc[4][8][4];
    #pragma unroll
    for (int mt = 0; mt < 4; mt++)
        #pragma unroll
        for (int nt = 0; nt < 8; nt++)
            #pragma unroll
            for (int q = 0; q < 4; q++) acc[mt][nt][q] = 0.f;

    // per-lane LDSM row components (in halfs)
    int arow = lane & 15;
    int akoff = (lane >> 4) * 8;
    int brow = (lane & 7) + ((lane & 16) ? 8 : 0);
    int bkoff = (lane & 8) ? 8 : 0;
    uint32_t rowA[4], rowB[4];
    #pragma unroll
    for (int mt = 0; mt < 4; mt++)
        rowA[mt] = (uint32_t)((wm * 64 + mt * 16 + arow) * HST2 + akoff) * 2;
    #pragma unroll
    for (int ntp = 0; ntp < 4; ntp++)
        rowB[ntp] = (uint32_t)((wn * 64 + ntp * 16 + brow) * HST2 + bkoff) * 2;

    uint32_t af[2][4][4], bf[2][4][4];     // double-buffered fragments

    #define LDF(buf, As, Ws, ks) do {                                        \
        uint32_t koff = (uint32_t)((ks) * 16 * 2);                           \
        _Pragma("unroll")                                                    \
        for (int mt = 0; mt < 4; mt++)                                       \
            ldsm4(af[buf][mt][0], af[buf][mt][1], af[buf][mt][2], af[buf][mt][3], \
                  (As) + rowA[mt] + koff);                                   \
        _Pragma("unroll")                                                    \
        for (int ntp = 0; ntp < 4; ntp++)                                    \
            ldsm4(bf[buf][ntp][0], bf[buf][ntp][1], bf[buf][ntp][2], bf[buf][ntp][3], \
                  (Ws) + rowB[ntp] + koff);                                  \
    } while (0)

    for (int i = 0; i < NIT; i++) {
        int s = i % 3;
        if (i + 1 < NIT) cp_wait<1>(); else cp_wait<0>();
        __syncthreads();
        if (i + 2 < NIT) ISSUE((i + 2) % 3, (i + 2) * 64);

        uint32_t As = sb + s * STG;
        uint32_t Ws = As + A_PL;

        LDF(0, As, Ws, 0);
        #pragma unroll
        for (int ks = 0; ks < 4; ks++) {
            int cur = ks & 1;
            if (ks < 3) LDF(cur ^ 1, As, Ws, ks + 1);
            #pragma unroll
            for (int ntp = 0; ntp < 4; ntp++) {
                uint32_t bA[2] = { bf[cur][ntp][0], bf[cur][ntp][1] };
                uint32_t bB[2] = { bf[cur][ntp][2], bf[cur][ntp][3] };
                #pragma unroll
                for (int mt = 0; mt < 4; mt++) {
                    mma_f16(acc[mt][2 * ntp],     af[cur][mt], bA);
                    mma_f16(acc[mt][2 * ntp + 1], af[cur][mt], bB);
                }
            }
        }
    }
    #undef ISSUE
    #undef LDF

    // epilogue
    #pragma unroll
    for (int mt = 0; mt < 4; mt++) {
        int m0 = bm + wm * 64 + mt * 16 + lr;
        #pragma unroll
        for (int nt = 0; nt < 8; nt++) {
            int n = bn + wn * 64 + nt * 8 + lc * 2;
            if (WHICH == 1) {
                __half* C0 = g_xz + (size_t)m0 * NTOT + n;
                __half* C1 = g_xz + (size_t)(m0 + 8) * NTOT + n;
                *(__half2*)C0 = __halves2half2(__float2half_rn(acc[mt][nt][0]),
                                               __float2half_rn(acc[mt][nt][1]));
                *(__half2*)C1 = __halves2half2(__float2half_rn(acc[mt][nt][2]),
                                               __float2half_rn(acc[mt][nt][3]));
            } else {
                float* C0 = Cout + (size_t)m0 * NTOT + n;
                float* C1 = Cout + (size_t)(m0 + 8) * NTOT + n;
                const float2 r0 = *(const float2*)(R + (size_t)m0 * NTOT + n);
                const float2 r1 = *(const float2*)(R + (size_t)(m0 + 8) * NTOT + n);
                *(float2*)C0 = make_float2(acc[mt][nt][0] + r0.x, acc[mt][nt][1] + r0.y);
                *(float2*)C1 = make_float2(acc[mt][nt][2] + r1.x, acc[mt][nt][3] + r1.y);
            }
        }
    }
}

// ======== chunked parallel scan: y_t = alpha*y_{t-1} + conv(x)_t (reads fp16 xz) ====
__global__ void __launch_bounds__(256) scan_p1(const float* __restrict__ conv_w,
                                               const float* __restrict__ conv_b,
                                               const float* __restrict__ log_alpha) {
    int idx = blockIdx.x * 256 + threadIdx.x;
    int c = idx & (DI - 1);
    int j = (idx >> 11) & (NC - 1);
    int b = idx >> 17;
    float w0 = conv_w[c * 4 + 0], w1 = conv_w[c * 4 + 1];
    float w2 = conv_w[c * 4 + 2], w3 = conv_w[c * 4 + 3];
    float bias = conv_b[c];
    float alpha = 1.f / (1.f + __expf(-log_alpha[c / HD]));

    const __half* xp = g_xz + (size_t)b * Ss * (2 * DI) + c;
    int t0 = j * CL;
    float h0 = (t0 >= 3) ? __half2float(xp[(size_t)(t0 - 3) * (2 * DI)]) : 0.f;
    float h1 = (t0 >= 2) ? __half2float(xp[(size_t)(t0 - 2) * (2 * DI)]) : 0.f;
    float h2 = (t0 >= 1) ? __half2float(xp[(size_t)(t0 - 1) * (2 * DI)]) : 0.f;

    float e = 0.f;
    #pragma unroll 4
    for (int t = t0; t < t0 + CL; t++) {
        float xt = __half2float(xp[(size_t)t * (2 * DI)]);
        float cv = fmaf(w0, h0, fmaf(w1, h1, fmaf(w2, h2, fmaf(w3, xt, bias))));
        h0 = h1; h1 = h2; h2 = xt;
        e = fmaf(alpha, e, cv);
    }
    g_e[idx] = e;
}

__global__ void __launch_bounds__(256) scan_p2(const float* __restrict__ log_alpha) {
    int idx = blockIdx.x * 256 + threadIdx.x;
    int c = idx & (DI - 1);
    int b = idx >> 11;
    float alpha = 1.f / (1.f + __expf(-log_alpha[c / HD]));
    float aL = powf(alpha, (float)CL);
    float s = 0.f;
    size_t base = (size_t)b * NC * DI + c;
    #pragma unroll 8
    for (int j = 0; j < NC; j++) {
        g_s[base + (size_t)j * DI] = s;
        s = fmaf(aL, s, g_e[base + (size_t)j * DI]);
    }
}

__global__ void __launch_bounds__(256) scan_p3(const float* __restrict__ conv_w,
                                               const float* __restrict__ conv_b,
                                               const float* __restrict__ log_alpha) {
    int idx = blockIdx.x * 256 + threadIdx.x;
    int c = idx & (DI - 1);
    int j = (idx >> 11) & (NC - 1);
    int b = idx >> 17;
    float w0 = conv_w[c * 4 + 0], w1 = conv_w[c * 4 + 1];
    float w2 = conv_w[c * 4 + 2], w3 = conv_w[c * 4 + 3];
    float bias = conv_b[c];
    float alpha = 1.f / (1.f + __expf(-log_alpha[c / HD]));

    const __half* xp = g_xz + (size_t)b * Ss * (2 * DI) + c;
    const __half* gp = xp + DI;
    size_t ao = (size_t)b * Ss * DI + c;
    int t0 = j * CL;
    float h0 = (t0 >= 3) ? __half2float(xp[(size_t)(t0 - 3) * (2 * DI)]) : 0.f;
    float h1 = (t0 >= 2) ? __half2float(xp[(size_t)(t0 - 2) * (2 * DI)]) : 0.f;
    float h2 = (t0 >= 1) ? __half2float(xp[(size_t)(t0 - 1) * (2 * DI)]) : 0.f;

    float y = g_s[idx];
    #pragma unroll 4
    for (int t = t0; t < t0 + CL; t++) {
        float xt = __half2float(xp[(size_t)t * (2 * DI)]);
        float g  = __half2float(gp[(size_t)t * (2 * DI)]);
        float cv = fmaf(w0, h0, fmaf(w1, h1, fmaf(w2, h2, fmaf(w3, xt, bias))));
        h0 = h1; h1 = h2; h2 = xt;
        y = fmaf(alpha, y, cv);
        float sl = y * (1.f / (1.f + __expf(-y)));
        g_acth[ao + (size_t)t * DI] = __float2half_rn(sl * g);
    }
}

// ---------------- launch (NO device-symbol references in host code) ----------------
extern "C" void kernel_launch(void* const* d_in, const int* in_sizes, int n_in,
                              void* d_out, int out_size) {
    const float* x          = (const float*)d_in[0];
    const float* norm_w     = (const float*)d_in[1];
    const float* norm_b     = (const float*)d_in[2];
    const float* in_proj_w  = (const float*)d_in[3];
    const float* conv_w     = (const float*)d_in[4];
    const float* conv_b     = (const float*)d_in[5];
    const float* out_proj_w = (const float*)d_in[6];
    const float* log_alpha  = (const float*)d_in[7];
    float* out = (float*)d_out;

    cudaFuncSetAttribute(gemm_h<1>, cudaFuncAttributeMaxDynamicSharedMemorySize, GEMM_SMEM);
    cudaFuncSetAttribute(gemm_h<2>, cudaFuncAttributeMaxDynamicSharedMemorySize, GEMM_SMEM);

    int n1 = 2 * DI * Dd / 4, n2 = Dd * DI / 4;
    wprep<1><<<(n1 + 255) / 256, 256>>>(in_proj_w);
    wprep<2><<<(n2 + 255) / 256, 256>>>(out_proj_w);

    ln_kernel<<<Mm, 256>>>(x, norm_w, norm_b);

    dim3 g1((2 * DI) / 128, Mm / 256);           // (32, 64)
    gemm_h<1><<<g1, 256, GEMM_SMEM>>>(nullptr, nullptr);

    scan_p1<<<(Bb * NC * DI) / 256, 256>>>(conv_w, conv_b, log_alpha);
    scan_p2<<<(Bb * DI) / 256, 256>>>(log_alpha);
    scan_p3<<<(Bb * NC * DI) / 256, 256>>>(conv_w, conv_b, log_alpha);

    dim3 g2(Dd / 128, Mm / 256);                 // (8, 64)
    gemm_h<2><<<g2, 256, GEMM_SMEM>>>(x, out);
}

// round 13
// speedup vs baseline: 8.6580x; 1.0276x over previous
#include <cuda_runtime.h>
#include <cuda_fp16.h>
#include <math.h>
#include <stdint.h>

#define Bb 4
#define Ss 4096
#define Dd 1024
#define DI 2048
#define HD 256
#define Mm (Bb * Ss)   // 16384 tokens
#define CL 64          // scan chunk length
#define NC (Ss / CL)   // 64 chunks

// ---------------- scratch (device-code references ONLY; never named in host code) ----
__device__ __half g_xz[(size_t)Mm * 2 * DI];     // 128 MB (gemm1 out, fp16)
__device__ __half g_xnh[(size_t)Mm * Dd];        //  32 MB (LN out, fp16)
__device__ __half g_acth[(size_t)Mm * DI];       //  64 MB (scan out, fp16)
__device__ __half g_w1h[(size_t)2 * DI * Dd];    //   8 MB (in_proj fp16)
__device__ __half g_w2h[(size_t)Dd * DI];        //   4 MB (out_proj fp16)
__device__ float g_e[(size_t)Bb * NC * DI];      //   2 MB (chunk end values)
__device__ float g_s[(size_t)Bb * NC * DI];      //   2 MB (chunk init states)

// ================= helpers =================
__device__ __forceinline__ uint32_t smem_u32(const void* p) {
    uint32_t a;
    asm("{ .reg .u64 t; cvta.to.shared.u64 t, %1; cvt.u32.u64 %0, t; }" : "=r"(a) : "l"(p));
    return a;
}
__device__ __forceinline__ void cp16(uint32_t dst, const void* src) {
    asm volatile("cp.async.cg.shared.global [%0], [%1], 16;" :: "r"(dst), "l"(src));
}
__device__ __forceinline__ void cp_commit() { asm volatile("cp.async.commit_group;" ::: "memory"); }
template <int N> __device__ __forceinline__ void cp_wait() {
    asm volatile("cp.async.wait_group %0;" :: "n"(N) : "memory");
}
__device__ __forceinline__ void ldsm4(uint32_t& r0, uint32_t& r1, uint32_t& r2, uint32_t& r3,
                                      uint32_t addr) {
    asm volatile("ldmatrix.sync.aligned.m8n8.x4.shared.b16 {%0,%1,%2,%3}, [%4];"
                 : "=r"(r0), "=r"(r1), "=r"(r2), "=r"(r3) : "r"(addr));
}
__device__ __forceinline__ void mma_f16(float* d, const uint32_t* a, const uint32_t* b) {
    asm volatile(
        "mma.sync.aligned.m16n8k16.row.col.f32.f16.f16.f32 "
        "{%0,%1,%2,%3}, {%4,%5,%6,%7}, {%8,%9}, {%0,%1,%2,%3};"
        : "+f"(d[0]), "+f"(d[1]), "+f"(d[2]), "+f"(d[3])
        : "r"(a[0]), "r"(a[1]), "r"(a[2]), "r"(a[3]), "r"(b[0]), "r"(b[1]));
}

// ---------------- weight round to fp16 ----------------
template <int WHICH>
__global__ void __launch_bounds__(256) wprep(const float* __restrict__ s) {
    __half* d = (WHICH == 1) ? g_w1h : g_w2h;
    const int n4 = (WHICH == 1) ? (2 * DI * Dd / 4) : (Dd * DI / 4);
    int i = blockIdx.x * 256 + threadIdx.x;
    if (i < n4) {
        float4 v = ((const float4*)s)[i];
        *(__half2*)(d + (size_t)i * 4)     = __halves2half2(__float2half_rn(v.x), __float2half_rn(v.y));
        *(__half2*)(d + (size_t)i * 4 + 2) = __halves2half2(__float2half_rn(v.z), __float2half_rn(v.w));
    }
}

// ---------------- LayerNorm (writes fp16) ----------------
__global__ void __launch_bounds__(256) ln_kernel(const float* __restrict__ x,
                                                 const float* __restrict__ w,
                                                 const float* __restrict__ bia) {
    int m = blockIdx.x;
    int t = threadIdx.x;
    const float4* xr = (const float4*)(x + (size_t)m * Dd);
    float4 xv = xr[t];
    float s  = xv.x + xv.y + xv.z + xv.w;
    float s2 = xv.x * xv.x + xv.y * xv.y + xv.z * xv.z + xv.w * xv.w;
    #pragma unroll
    for (int o = 16; o; o >>= 1) {
        s  += __shfl_xor_sync(0xffffffffu, s, o);
        s2 += __shfl_xor_sync(0xffffffffu, s2, o);
    }
    __shared__ float shs[8], shs2[8];
    int wid = t >> 5, lane = t & 31;
    if (lane == 0) { shs[wid] = s; shs2[wid] = s2; }
    __syncthreads();
    s = 0.f; s2 = 0.f;
    #pragma unroll
    for (int i = 0; i < 8; i++) { s += shs[i]; s2 += shs2[i]; }
    float mu  = s * (1.0f / Dd);
    float var = s2 * (1.0f / Dd) - mu * mu;
    float rstd = rsqrtf(var + 1e-5f);
    float4 wv = ((const float4*)w)[t];
    float4 bv = ((const float4*)bia)[t];
    float o0 = (xv.x - mu) * rstd * wv.x + bv.x;
    float o1 = (xv.y - mu) * rstd * wv.y + bv.y;
    float o2 = (xv.z - mu) * rstd * wv.z + bv.z;
    float o3 = (xv.w - mu) * rstd * wv.w + bv.w;
    size_t base = (size_t)m * Dd + 4 * t;
    *(__half2*)(g_xnh + base)     = __halves2half2(__float2half_rn(o0), __float2half_rn(o1));
    *(__half2*)(g_xnh + base + 2) = __halves2half2(__float2half_rn(o2), __float2half_rn(o3));
}

// ==== fp16 GEMM: CTA 128x128 (128 thr, 4 warps 2x2), warp 64x64, BK=64, 3-stage ====
// 2 CTAs/SM: independent barrier seams overlap -> tensor pipe stays fed.
#define HST2 72
#define A_PL (128 * HST2 * 2)              // 18432
#define STG  (2 * A_PL)                    // 36864 (A + B planes)
#define GEMM_SMEM (3 * STG)                // 110592 per CTA

template <int WHICH>                        // 1: xn @ w1 -> g_xz(half) ; 2: act @ w2 + R -> out(f32)
__global__ void __launch_bounds__(128, 2) gemm_h(const float* __restrict__ R,
                                                 float* __restrict__ Cout) {
    constexpr int NTOT = (WHICH == 1) ? 2 * DI : Dd;
    constexpr int KK   = (WHICH == 1) ? Dd : DI;
    const __half* Ap = (WHICH == 1) ? g_xnh : g_acth;
    const __half* Wp = (WHICH == 1) ? g_w1h : g_w2h;

    extern __shared__ char smraw[];
    uint32_t sb = smem_u32(smraw);
    int tid = threadIdx.x, lane = tid & 31, wid = tid >> 5;
    int wm = wid & 1, wn = wid >> 1;               // 2 x 2
    int bm = blockIdx.y * 128, bn = blockIdx.x * 128;
    int lr = lane >> 2, lc = lane & 3;

    // producers: 128 threads; A 128 rows x 8 chunks + B 128 rows x 8 chunks = 16/thread
    int pr = tid >> 3, pc = (tid & 7) * 8;          // pr 0..15, pc halfs
    const __half* pA = Ap + (size_t)(bm + pr) * KK + pc;
    const __half* pW = Wp + (size_t)(bn + pr) * KK + pc;
    uint32_t dA = sb + (uint32_t)(pr * HST2 + pc) * 2;
    uint32_t dW = dA + A_PL;

    const int NIT = KK / 64;
    #define ISSUE(s, k0) do {                                                       \
        _Pragma("unroll")                                                           \
        for (int j = 0; j < 8; j++) {                                               \
            cp16(dA + (s) * STG + j * 16 * HST2 * 2, pA + (size_t)j * 16 * KK + (k0)); \
            cp16(dW + (s) * STG + j * 16 * HST2 * 2, pW + (size_t)j * 16 * KK + (k0)); \
        }                                                                           \
        cp_commit();                                                                \
    } while (0)

    ISSUE(0, 0);
    ISSUE(1, 64);

    float acc[4][8][4];
    #pragma unroll
    for (int mt = 0; mt < 4; mt++)
        #pragma unroll
        for (int nt = 0; nt < 8; nt++)
            #pragma unroll
            for (int q = 0; q < 4; q++) acc[mt][nt][q] = 0.f;

    // per-lane LDSM row components (in halfs)
    int arow = lane & 15;
    int akoff = (lane >> 4) * 8;
    int brow = (lane & 7) + ((lane & 16) ? 8 : 0);
    int bkoff = (lane & 8) ? 8 : 0;
    uint32_t rowA[4], rowB[4];
    #pragma unroll
    for (int mt = 0; mt < 4; mt++)
        rowA[mt] = (uint32_t)((wm * 64 + mt * 16 + arow) * HST2 + akoff) * 2;
    #pragma unroll
    for (int ntp = 0; ntp < 4; ntp++)
        rowB[ntp] = (uint32_t)((wn * 64 + ntp * 16 + brow) * HST2 + bkoff) * 2;

    uint32_t af[2][4][4], bf[2][4][4];

    #define LDF(buf, As, Ws, ks) do {                                        \
        uint32_t koff = (uint32_t)((ks) * 16 * 2);                           \
        _Pragma("unroll")                                                    \
        for (int mt = 0; mt < 4; mt++)                                       \
            ldsm4(af[buf][mt][0], af[buf][mt][1], af[buf][mt][2], af[buf][mt][3], \
                  (As) + rowA[mt] + koff);                                   \
        _Pragma("unroll")                                                    \
        for (int ntp = 0; ntp < 4; ntp++)                                    \
            ldsm4(bf[buf][ntp][0], bf[buf][ntp][1], bf[buf][ntp][2], bf[buf][ntp][3], \
                  (Ws) + rowB[ntp] + koff);                                  \
    } while (0)

    for (int i = 0; i < NIT; i++) {
        int s = i % 3;
        if (i + 1 < NIT) cp_wait<1>(); else cp_wait<0>();
        __syncthreads();
        if (i + 2 < NIT) ISSUE((i + 2) % 3, (i + 2) * 64);

        uint32_t As = sb + s * STG;
        uint32_t Ws = As + A_PL;

        LDF(0, As, Ws, 0);
        #pragma unroll
        for (int ks = 0; ks < 4; ks++) {
            int cur = ks & 1;
            if (ks < 3) LDF(cur ^ 1, As, Ws, ks + 1);
            #pragma unroll
            for (int ntp = 0; ntp < 4; ntp++) {
                uint32_t bA[2] = { bf[cur][ntp][0], bf[cur][ntp][1] };
                uint32_t bB[2] = { bf[cur][ntp][2], bf[cur][ntp][3] };
                #pragma unroll
                for (int mt = 0; mt < 4; mt++) {
                    mma_f16(acc[mt][2 * ntp],     af[cur][mt], bA);
                    mma_f16(acc[mt][2 * ntp + 1], af[cur][mt], bB);
                }
            }
        }
    }
    #undef ISSUE
    #undef LDF

    // epilogue
    #pragma unroll
    for (int mt = 0; mt < 4; mt++) {
        int m0 = bm + wm * 64 + mt * 16 + lr;
        #pragma unroll
        for (int nt = 0; nt < 8; nt++) {
            int n = bn + wn * 64 + nt * 8 + lc * 2;
            if (WHICH == 1) {
                __half* C0 = g_xz + (size_t)m0 * NTOT + n;
                __half* C1 = g_xz + (size_t)(m0 + 8) * NTOT + n;
                *(__half2*)C0 = __halves2half2(__float2half_rn(acc[mt][nt][0]),
                                               __float2half_rn(acc[mt][nt][1]));
                *(__half2*)C1 = __halves2half2(__float2half_rn(acc[mt][nt][2]),
                                               __float2half_rn(acc[mt][nt][3]));
            } else {
                float* C0 = Cout + (size_t)m0 * NTOT + n;
                float* C1 = Cout + (size_t)(m0 + 8) * NTOT + n;
                const float2 r0 = *(const float2*)(R + (size_t)m0 * NTOT + n);
                const float2 r1 = *(const float2*)(R + (size_t)(m0 + 8) * NTOT + n);
                *(float2*)C0 = make_float2(acc[mt][nt][0] + r0.x, acc[mt][nt][1] + r0.y);
                *(float2*)C1 = make_float2(acc[mt][nt][2] + r1.x, acc[mt][nt][3] + r1.y);
            }
        }
    }
}

// ======== chunked parallel scan: y_t = alpha*y_{t-1} + conv(x)_t (reads fp16 xz) ====
__global__ void __launch_bounds__(256) scan_p1(const float* __restrict__ conv_w,
                                               const float* __restrict__ conv_b,
                                               const float* __restrict__ log_alpha) {
    int idx = blockIdx.x * 256 + threadIdx.x;
    int c = idx & (DI - 1);
    int j = (idx >> 11) & (NC - 1);
    int b = idx >> 17;
    float w0 = conv_w[c * 4 + 0], w1 = conv_w[c * 4 + 1];
    float w2 = conv_w[c * 4 + 2], w3 = conv_w[c * 4 + 3];
    float bias = conv_b[c];
    float alpha = 1.f / (1.f + __expf(-log_alpha[c / HD]));

    const __half* xp = g_xz + (size_t)b * Ss * (2 * DI) + c;
    int t0 = j * CL;
    float h0 = (t0 >= 3) ? __half2float(xp[(size_t)(t0 - 3) * (2 * DI)]) : 0.f;
    float h1 = (t0 >= 2) ? __half2float(xp[(size_t)(t0 - 2) * (2 * DI)]) : 0.f;
    float h2 = (t0 >= 1) ? __half2float(xp[(size_t)(t0 - 1) * (2 * DI)]) : 0.f;

    float e = 0.f;
    #pragma unroll 4
    for (int t = t0; t < t0 + CL; t++) {
        float xt = __half2float(xp[(size_t)t * (2 * DI)]);
        float cv = fmaf(w0, h0, fmaf(w1, h1, fmaf(w2, h2, fmaf(w3, xt, bias))));
        h0 = h1; h1 = h2; h2 = xt;
        e = fmaf(alpha, e, cv);
    }
    g_e[idx] = e;
}

__global__ void __launch_bounds__(256) scan_p2(const float* __restrict__ log_alpha) {
    int idx = blockIdx.x * 256 + threadIdx.x;
    int c = idx & (DI - 1);
    int b = idx >> 11;
    float alpha = 1.f / (1.f + __expf(-log_alpha[c / HD]));
    float aL = powf(alpha, (float)CL);
    float s = 0.f;
    size_t base = (size_t)b * NC * DI + c;
    #pragma unroll 8
    for (int j = 0; j < NC; j++) {
        g_s[base + (size_t)j * DI] = s;
        s = fmaf(aL, s, g_e[base + (size_t)j * DI]);
    }
}

__global__ void __launch_bounds__(256) scan_p3(const float* __restrict__ conv_w,
                                               const float* __restrict__ conv_b,
                                               const float* __restrict__ log_alpha) {
    int idx = blockIdx.x * 256 + threadIdx.x;
    int c = idx & (DI - 1);
    int j = (idx >> 11) & (NC - 1);
    int b = idx >> 17;
    float w0 = conv_w[c * 4 + 0], w1 = conv_w[c * 4 + 1];
    float w2 = conv_w[c * 4 + 2], w3 = conv_w[c * 4 + 3];
    float bias = conv_b[c];
    float alpha = 1.f / (1.f + __expf(-log_alpha[c / HD]));

    const __half* xp = g_xz + (size_t)b * Ss * (2 * DI) + c;
    const __half* gp = xp + DI;
    size_t ao = (size_t)b * Ss * DI + c;
    int t0 = j * CL;
    float h0 = (t0 >= 3) ? __half2float(xp[(size_t)(t0 - 3) * (2 * DI)]) : 0.f;
    float h1 = (t0 >= 2) ? __half2float(xp[(size_t)(t0 - 2) * (2 * DI)]) : 0.f;
    float h2 = (t0 >= 1) ? __half2float(xp[(size_t)(t0 - 1) * (2 * DI)]) : 0.f;

    float y = g_s[idx];
    #pragma unroll 4
    for (int t = t0; t < t0 + CL; t++) {
        float xt = __half2float(xp[(size_t)t * (2 * DI)]);
        float g  = __half2float(gp[(size_t)t * (2 * DI)]);
        float cv = fmaf(w0, h0, fmaf(w1, h1, fmaf(w2, h2, fmaf(w3, xt, bias))));
        h0 = h1; h1 = h2; h2 = xt;
        y = fmaf(alpha, y, cv);
        float sl = y * (1.f / (1.f + __expf(-y)));
        g_acth[ao + (size_t)t * DI] = __float2half_rn(sl * g);
    }
}

// ---------------- launch (NO device-symbol references in host code) ----------------
extern "C" void kernel_launch(void* const* d_in, const int* in_sizes, int n_in,
                              void* d_out, int out_size) {
    const float* x          = (const float*)d_in[0];
    const float* norm_w     = (const float*)d_in[1];
    const float* norm_b     = (const float*)d_in[2];
    const float* in_proj_w  = (const float*)d_in[3];
    const float* conv_w     = (const float*)d_in[4];
    const float* conv_b     = (const float*)d_in[5];
    const float* out_proj_w = (const float*)d_in[6];
    const float* log_alpha  = (const float*)d_in[7];
    float* out = (float*)d_out;

    cudaFuncSetAttribute(gemm_h<1>, cudaFuncAttributeMaxDynamicSharedMemorySize, GEMM_SMEM);
    cudaFuncSetAttribute(gemm_h<2>, cudaFuncAttributeMaxDynamicSharedMemorySize, GEMM_SMEM);

    int n1 = 2 * DI * Dd / 4, n2 = Dd * DI / 4;
    wprep<1><<<(n1 + 255) / 256, 256>>>(in_proj_w);
    wprep<2><<<(n2 + 255) / 256, 256>>>(out_proj_w);

    ln_kernel<<<Mm, 256>>>(x, norm_w, norm_b);

    dim3 g1((2 * DI) / 128, Mm / 128);           // (32, 128)
    gemm_h<1><<<g1, 128, GEMM_SMEM>>>(nullptr, nullptr);

    scan_p1<<<(Bb * NC * DI) / 256, 256>>>(conv_w, conv_b, log_alpha);
    scan_p2<<<(Bb * DI) / 256, 256>>>(log_alpha);
    scan_p3<<<(Bb * NC * DI) / 256, 256>>>(conv_w, conv_b, log_alpha);

    dim3 g2(Dd / 128, Mm / 128);                 // (8, 128)
    gemm_h<2><<<g2, 128, GEMM_SMEM>>>(x, out);
}

// round 14
// speedup vs baseline: 9.1228x; 1.0537x over previous
#include <cuda_runtime.h>
#include <cuda_fp16.h>
#include <math.h>
#include <stdint.h>

#define Bb 4
#define Ss 4096
#define Dd 1024
#define DI 2048
#define HD 256
#define Mm (Bb * Ss)   // 16384 tokens
#define CL 64          // scan chunk length
#define NC (Ss / CL)   // 64 chunks

// ---------------- scratch (device-code references ONLY; never named in host code) ----
__device__ __half g_xz[(size_t)Mm * 2 * DI];     // 128 MB (gemm1 out, fp16)
__device__ __half g_xnh[(size_t)Mm * Dd];        //  32 MB (LN out, fp16)
__device__ __half g_acth[(size_t)Mm * DI];       //  64 MB (scan out, fp16)
__device__ __half g_w1h[(size_t)2 * DI * Dd];    //   8 MB (in_proj fp16)
__device__ __half g_w2h[(size_t)Dd * DI];        //   4 MB (out_proj fp16)
__device__ float g_e[(size_t)Bb * NC * DI];      //   2 MB (chunk end values)
__device__ float g_s[(size_t)Bb * NC * DI];      //   2 MB (chunk init states)

// ================= helpers =================
__device__ __forceinline__ uint32_t smem_u32(const void* p) {
    uint32_t a;
    asm("{ .reg .u64 t; cvta.to.shared.u64 t, %1; cvt.u32.u64 %0, t; }" : "=r"(a) : "l"(p));
    return a;
}
__device__ __forceinline__ void cp16(uint32_t dst, const void* src) {
    asm volatile("cp.async.cg.shared.global [%0], [%1], 16;" :: "r"(dst), "l"(src));
}
__device__ __forceinline__ void cp_commit() { asm volatile("cp.async.commit_group;" ::: "memory"); }
template <int N> __device__ __forceinline__ void cp_wait() {
    asm volatile("cp.async.wait_group %0;" :: "n"(N) : "memory");
}
__device__ __forceinline__ void ldsm4(uint32_t& r0, uint32_t& r1, uint32_t& r2, uint32_t& r3,
                                      uint32_t addr) {
    asm volatile("ldmatrix.sync.aligned.m8n8.x4.shared.b16 {%0,%1,%2,%3}, [%4];"
                 : "=r"(r0), "=r"(r1), "=r"(r2), "=r"(r3) : "r"(addr));
}
__device__ __forceinline__ void mma_f16(float* d, const uint32_t* a, const uint32_t* b) {
    asm volatile(
        "mma.sync.aligned.m16n8k16.row.col.f32.f16.f16.f32 "
        "{%0,%1,%2,%3}, {%4,%5,%6,%7}, {%8,%9}, {%0,%1,%2,%3};"
        : "+f"(d[0]), "+f"(d[1]), "+f"(d[2]), "+f"(d[3])
        : "r"(a[0]), "r"(a[1]), "r"(a[2]), "r"(a[3]), "r"(b[0]), "r"(b[1]));
}

// ---------------- weight round to fp16 ----------------
template <int WHICH>
__global__ void __launch_bounds__(256) wprep(const float* __restrict__ s) {
    __half* d = (WHICH == 1) ? g_w1h : g_w2h;
    const int n4 = (WHICH == 1) ? (2 * DI * Dd / 4) : (Dd * DI / 4);
    int i = blockIdx.x * 256 + threadIdx.x;
    if (i < n4) {
        float4 v = ((const float4*)s)[i];
        *(__half2*)(d + (size_t)i * 4)     = __halves2half2(__float2half_rn(v.x), __float2half_rn(v.y));
        *(__half2*)(d + (size_t)i * 4 + 2) = __halves2half2(__float2half_rn(v.z), __float2half_rn(v.w));
    }
}

// ---------------- LayerNorm (writes fp16) ----------------
__global__ void __launch_bounds__(256) ln_kernel(const float* __restrict__ x,
                                                 const float* __restrict__ w,
                                                 const float* __restrict__ bia) {
    int m = blockIdx.x;
    int t = threadIdx.x;
    const float4* xr = (const float4*)(x + (size_t)m * Dd);
    float4 xv = xr[t];
    float s  = xv.x + xv.y + xv.z + xv.w;
    float s2 = xv.x * xv.x + xv.y * xv.y + xv.z * xv.z + xv.w * xv.w;
    #pragma unroll
    for (int o = 16; o; o >>= 1) {
        s  += __shfl_xor_sync(0xffffffffu, s, o);
        s2 += __shfl_xor_sync(0xffffffffu, s2, o);
    }
    __shared__ float shs[8], shs2[8];
    int wid = t >> 5, lane = t & 31;
    if (lane == 0) { shs[wid] = s; shs2[wid] = s2; }
    __syncthreads();
    s = 0.f; s2 = 0.f;
    #pragma unroll
    for (int i = 0; i < 8; i++) { s += shs[i]; s2 += shs2[i]; }
    float mu  = s * (1.0f / Dd);
    float var = s2 * (1.0f / Dd) - mu * mu;
    float rstd = rsqrtf(var + 1e-5f);
    float4 wv = ((const float4*)w)[t];
    float4 bv = ((const float4*)bia)[t];
    float o0 = (xv.x - mu) * rstd * wv.x + bv.x;
    float o1 = (xv.y - mu) * rstd * wv.y + bv.y;
    float o2 = (xv.z - mu) * rstd * wv.z + bv.z;
    float o3 = (xv.w - mu) * rstd * wv.w + bv.w;
    size_t base = (size_t)m * Dd + 4 * t;
    *(__half2*)(g_xnh + base)     = __halves2half2(__float2half_rn(o0), __float2half_rn(o1));
    *(__half2*)(g_xnh + base + 2) = __halves2half2(__float2half_rn(o2), __float2half_rn(o3));
}

// ==== fp16 GEMM: CTA 128x128 (256 thr, 8 warps 2m x 4n), warp 64x32, BK=64, 3-stage ====
// 2 CTAs/SM -> 16 warps/SM (4 per SMSP): enough concurrent mma streams to fill the pipe.
#define HST2 72
#define A_PL (128 * HST2 * 2)              // 18432
#define STG  (2 * A_PL)                    // 36864 (A + B planes)
#define GEMM_SMEM (3 * STG)                // 110592 per CTA

template <int WHICH>                        // 1: xn @ w1 -> g_xz(half) ; 2: act @ w2 + R -> out(f32)
__global__ void __launch_bounds__(256, 2) gemm_h(const float* __restrict__ R,
                                                 float* __restrict__ Cout) {
    constexpr int NTOT = (WHICH == 1) ? 2 * DI : Dd;
    constexpr int KK   = (WHICH == 1) ? Dd : DI;
    const __half* Ap = (WHICH == 1) ? g_xnh : g_acth;
    const __half* Wp = (WHICH == 1) ? g_w1h : g_w2h;

    extern __shared__ char smraw[];
    uint32_t sb = smem_u32(smraw);
    int tid = threadIdx.x, lane = tid & 31, wid = tid >> 5;
    int wm = wid & 1, wn = wid >> 1;               // 2 x 4
    int bm = blockIdx.y * 128, bn = blockIdx.x * 128;
    int lr = lane >> 2, lc = lane & 3;

    // producers: 256 threads; A 128 rows x 8 chunks (1024) + B same -> 4+4 per thread
    int pr = tid >> 3, pc = (tid & 7) * 8;          // pr 0..31, pc halfs
    const __half* pA = Ap + (size_t)(bm + pr) * KK + pc;
    const __half* pW = Wp + (size_t)(bn + pr) * KK + pc;
    uint32_t dA = sb + (uint32_t)(pr * HST2 + pc) * 2;
    uint32_t dW = dA + A_PL;

    const int NIT = KK / 64;
    #define ISSUE(s, k0) do {                                                       \
        _Pragma("unroll")                                                           \
        for (int j = 0; j < 4; j++) {                                               \
            cp16(dA + (s) * STG + j * 32 * HST2 * 2, pA + (size_t)j * 32 * KK + (k0)); \
            cp16(dW + (s) * STG + j * 32 * HST2 * 2, pW + (size_t)j * 32 * KK + (k0)); \
        }                                                                           \
        cp_commit();                                                                \
    } while (0)

    ISSUE(0, 0);
    ISSUE(1, 64);

    float acc[4][4][4];                             // mt x nt(4 of 8 cols) x quad
    #pragma unroll
    for (int mt = 0; mt < 4; mt++)
        #pragma unroll
        for (int nt = 0; nt < 4; nt++)
            #pragma unroll
            for (int q = 0; q < 4; q++) acc[mt][nt][q] = 0.f;

    // per-lane LDSM row components (in halfs)
    int arow = lane & 15;
    int akoff = (lane >> 4) * 8;
    int brow = (lane & 7) + ((lane & 16) ? 8 : 0);
    int bkoff = (lane & 8) ? 8 : 0;
    uint32_t rowA[4], rowB[2];
    #pragma unroll
    for (int mt = 0; mt < 4; mt++)
        rowA[mt] = (uint32_t)((wm * 64 + mt * 16 + arow) * HST2 + akoff) * 2;
    #pragma unroll
    for (int ntp = 0; ntp < 2; ntp++)
        rowB[ntp] = (uint32_t)((wn * 32 + ntp * 16 + brow) * HST2 + bkoff) * 2;

    for (int i = 0; i < NIT; i++) {
        int s = i % 3;
        if (i + 1 < NIT) cp_wait<1>(); else cp_wait<0>();
        __syncthreads();
        if (i + 2 < NIT) ISSUE((i + 2) % 3, (i + 2) * 64);

        uint32_t As = sb + s * STG;
        uint32_t Ws = As + A_PL;

        #pragma unroll
        for (int ks = 0; ks < 4; ks++) {
            uint32_t koff = (uint32_t)(ks * 16 * 2);
            uint32_t a[4][4], b[2][4];
            #pragma unroll
            for (int mt = 0; mt < 4; mt++)
                ldsm4(a[mt][0], a[mt][1], a[mt][2], a[mt][3], As + rowA[mt] + koff);
            #pragma unroll
            for (int ntp = 0; ntp < 2; ntp++)
                ldsm4(b[ntp][0], b[ntp][1], b[ntp][2], b[ntp][3], Ws + rowB[ntp] + koff);
            #pragma unroll
            for (int ntp = 0; ntp < 2; ntp++) {
                uint32_t bA[2] = { b[ntp][0], b[ntp][1] };
                uint32_t bB[2] = { b[ntp][2], b[ntp][3] };
                #pragma unroll
                for (int mt = 0; mt < 4; mt++) {
                    mma_f16(acc[mt][2 * ntp],     a[mt], bA);
                    mma_f16(acc[mt][2 * ntp + 1], a[mt], bB);
                }
            }
        }
    }
    #undef ISSUE

    // epilogue: warp covers rows wm*64..+63, cols wn*32..+31
    #pragma unroll
    for (int mt = 0; mt < 4; mt++) {
        int m0 = bm + wm * 64 + mt * 16 + lr;
        #pragma unroll
        for (int nt = 0; nt < 4; nt++) {
            int n = bn + wn * 32 + nt * 8 + lc * 2;
            if (WHICH == 1) {
                __half* C0 = g_xz + (size_t)m0 * NTOT + n;
                __half* C1 = g_xz + (size_t)(m0 + 8) * NTOT + n;
                *(__half2*)C0 = __halves2half2(__float2half_rn(acc[mt][nt][0]),
                                               __float2half_rn(acc[mt][nt][1]));
                *(__half2*)C1 = __halves2half2(__float2half_rn(acc[mt][nt][2]),
                                               __float2half_rn(acc[mt][nt][3]));
            } else {
                float* C0 = Cout + (size_t)m0 * NTOT + n;
                float* C1 = Cout + (size_t)(m0 + 8) * NTOT + n;
                const float2 r0 = *(const float2*)(R + (size_t)m0 * NTOT + n);
                const float2 r1 = *(const float2*)(R + (size_t)(m0 + 8) * NTOT + n);
                *(float2*)C0 = make_float2(acc[mt][nt][0] + r0.x, acc[mt][nt][1] + r0.y);
                *(float2*)C1 = make_float2(acc[mt][nt][2] + r1.x, acc[mt][nt][3] + r1.y);
            }
        }
    }
}

// ======== chunked parallel scan: y_t = alpha*y_{t-1} + conv(x)_t (reads fp16 xz) ====
__global__ void __launch_bounds__(256) scan_p1(const float* __restrict__ conv_w,
                                               const float* __restrict__ conv_b,
                                               const float* __restrict__ log_alpha) {
    int idx = blockIdx.x * 256 + threadIdx.x;
    int c = idx & (DI - 1);
    int j = (idx >> 11) & (NC - 1);
    int b = idx >> 17;
    float w0 = conv_w[c * 4 + 0], w1 = conv_w[c * 4 + 1];
    float w2 = conv_w[c * 4 + 2], w3 = conv_w[c * 4 + 3];
    float bias = conv_b[c];
    float alpha = 1.f / (1.f + __expf(-log_alpha[c / HD]));

    const __half* xp = g_xz + (size_t)b * Ss * (2 * DI) + c;
    int t0 = j * CL;
    float h0 = (t0 >= 3) ? __half2float(xp[(size_t)(t0 - 3) * (2 * DI)]) : 0.f;
    float h1 = (t0 >= 2) ? __half2float(xp[(size_t)(t0 - 2) * (2 * DI)]) : 0.f;
    float h2 = (t0 >= 1) ? __half2float(xp[(size_t)(t0 - 1) * (2 * DI)]) : 0.f;

    float e = 0.f;
    #pragma unroll 4
    for (int t = t0; t < t0 + CL; t++) {
        float xt = __half2float(xp[(size_t)t * (2 * DI)]);
        float cv = fmaf(w0, h0, fmaf(w1, h1, fmaf(w2, h2, fmaf(w3, xt, bias))));
        h0 = h1; h1 = h2; h2 = xt;
        e = fmaf(alpha, e, cv);
    }
    g_e[idx] = e;
}

__global__ void __launch_bounds__(256) scan_p2(const float* __restrict__ log_alpha) {
    int idx = blockIdx.x * 256 + threadIdx.x;
    int c = idx & (DI - 1);
    int b = idx >> 11;
    float alpha = 1.f / (1.f + __expf(-log_alpha[c / HD]));
    float aL = powf(alpha, (float)CL);
    float s = 0.f;
    size_t base = (size_t)b * NC * DI + c;
    #pragma unroll 8
    for (int j = 0; j < NC; j++) {
        g_s[base + (size_t)j * DI] = s;
        s = fmaf(aL, s, g_e[base + (size_t)j * DI]);
    }
}

__global__ void __launch_bounds__(256) scan_p3(const float* __restrict__ conv_w,
                                               const float* __restrict__ conv_b,
                                               const float* __restrict__ log_alpha) {
    int idx = blockIdx.x * 256 + threadIdx.x;
    int c = idx & (DI - 1);
    int j = (idx >> 11) & (NC - 1);
    int b = idx >> 17;
    float w0 = conv_w[c * 4 + 0], w1 = conv_w[c * 4 + 1];
    float w2 = conv_w[c * 4 + 2], w3 = conv_w[c * 4 + 3];
    float bias = conv_b[c];
    float alpha = 1.f / (1.f + __expf(-log_alpha[c / HD]));

    const __half* xp = g_xz + (size_t)b * Ss * (2 * DI) + c;
    const __half* gp = xp + DI;
    size_t ao = (size_t)b * Ss * DI + c;
    int t0 = j * CL;
    float h0 = (t0 >= 3) ? __half2float(xp[(size_t)(t0 - 3) * (2 * DI)]) : 0.f;
    float h1 = (t0 >= 2) ? __half2float(xp[(size_t)(t0 - 2) * (2 * DI)]) : 0.f;
    float h2 = (t0 >= 1) ? __half2float(xp[(size_t)(t0 - 1) * (2 * DI)]) : 0.f;

    float y = g_s[idx];
    #pragma unroll 4
    for (int t = t0; t < t0 + CL; t++) {
        float xt = __half2float(xp[(size_t)t * (2 * DI)]);
        float g  = __half2float(gp[(size_t)t * (2 * DI)]);
        float cv = fmaf(w0, h0, fmaf(w1, h1, fmaf(w2, h2, fmaf(w3, xt, bias))));
        h0 = h1; h1 = h2; h2 = xt;
        y = fmaf(alpha, y, cv);
        float sl = y * (1.f / (1.f + __expf(-y)));
        g_acth[ao + (size_t)t * DI] = __float2half_rn(sl * g);
    }
}

// ---------------- launch (NO device-symbol references in host code) ----------------
extern "C" void kernel_launch(void* const* d_in, const int* in_sizes, int n_in,
                              void* d_out, int out_size) {
    const float* x          = (const float*)d_in[0];
    const float* norm_w     = (const float*)d_in[1];
    const float* norm_b     = (const float*)d_in[2];
    const float* in_proj_w  = (const float*)d_in[3];
    const float* conv_w     = (const float*)d_in[4];
    const float* conv_b     = (const float*)d_in[5];
    const float* out_proj_w = (const float*)d_in[6];
    const float* log_alpha  = (const float*)d_in[7];
    float* out = (float*)d_out;

    cudaFuncSetAttribute(gemm_h<1>, cudaFuncAttributeMaxDynamicSharedMemorySize, GEMM_SMEM);
    cudaFuncSetAttribute(gemm_h<2>, cudaFuncAttributeMaxDynamicSharedMemorySize, GEMM_SMEM);

    int n1 = 2 * DI * Dd / 4, n2 = Dd * DI / 4;
    wprep<1><<<(n1 + 255) / 256, 256>>>(in_proj_w);
    wprep<2><<<(n2 + 255) / 256, 256>>>(out_proj_w);

    ln_kernel<<<Mm, 256>>>(x, norm_w, norm_b);

    dim3 g1((2 * DI) / 128, Mm / 128);           // (32, 128)
    gemm_h<1><<<g1, 256, GEMM_SMEM>>>(nullptr, nullptr);

    scan_p1<<<(Bb * NC * DI) / 256, 256>>>(conv_w, conv_b, log_alpha);
    scan_p2<<<(Bb * DI) / 256, 256>>>(log_alpha);
    scan_p3<<<(Bb * NC * DI) / 256, 256>>>(conv_w, conv_b, log_alpha);

    dim3 g2(Dd / 128, Mm / 128);                 // (8, 128)
    gemm_h<2><<<g2, 256, GEMM_SMEM>>>(x, out);
}